// round 6
// baseline (speedup 1.0000x reference)
#include <cuda_runtime.h>
#include <math.h>
#include <float.h>

// Problem constants
#define B_   4
#define T_   2048
#define C_   1024
#define H_   16
#define D_   64
#define BT_  (B_*T_)           // 8192
#define F3_  (3*C_)            // 3072

// Scratch (static device globals: alloc-free, graph-safe)
__device__ float g_qkv[(size_t)BT_ * F3_];        // [B*T, 3C]
__device__ float g_q[(size_t)B_*H_*T_*D_];        // [B,H,T,D]
__device__ float g_k[(size_t)B_*H_*T_*D_];
__device__ float g_v[(size_t)B_*H_*T_*D_];
__device__ float g_y[(size_t)BT_ * C_];           // [B,T,C]

// FFMA-only exp2: avoids MUFU (rt_SMSP=8 -> 0.5 op/cyc/SM would bottleneck
// 134M exps at ~1ms chip-wide). Degree-5 Taylor on [-0.5,0.5], rel err ~2e-6.
// Input is always <= 0 here; -inf clamps to -126 -> ~1.2e-38 ~ 0.
__device__ __forceinline__ float fexp2(float x) {
    x = fmaxf(x, -126.f);
    float fl = rintf(x);
    float fr = x - fl;                  // in [-0.5, 0.5]
    float p = 0.0013333558f;
    p = fmaf(p, fr, 0.0096181291f);
    p = fmaf(p, fr, 0.0555041087f);
    p = fmaf(p, fr, 0.2402265069f);
    p = fmaf(p, fr, 0.6931471806f);
    p = fmaf(p, fr, 1.0f);
    return __int_as_float(__float_as_int(p) + (((int)fl) << 23));
}

// ---------------------------------------------------------------------------
// SGEMM: C[M,N] = A[M,K] @ B[K,N], row-major, fp32. Tiles 128x128, BK=8,
// 256 threads, 8x8 micro-tile. Double-buffered smem, one sync per K-step.
// ---------------------------------------------------------------------------
__global__ __launch_bounds__(256) void sgemm_k(
    const float* __restrict__ A, const float* __restrict__ B,
    float* __restrict__ C, int M, int N, int K)
{
    __shared__ float As[2][8][128];
    __shared__ float Bs[2][8][128];

    const int tid = threadIdx.x;
    const int bm = blockIdx.y * 128;
    const int bn = blockIdx.x * 128;

    const int a_row = tid >> 1;           // 0..127
    const int a_col = (tid & 1) * 4;      // 0 or 4
    const int b_row = tid >> 5;           // 0..7
    const int b_col = (tid & 31) * 4;     // 0..124

    const float* Aptr = A + (size_t)(bm + a_row) * K + a_col;
    const float* Bptr = B + (size_t)b_row * N + bn + b_col;

    const int tm = (tid >> 4) * 8;        // 0..120
    const int tn = (tid & 15) * 8;        // 0..120

    float acc[8][8];
#pragma unroll
    for (int i = 0; i < 8; ++i)
#pragma unroll
        for (int j = 0; j < 8; ++j) acc[i][j] = 0.f;

    // Preload tile 0
    {
        float4 av = *(const float4*)Aptr;  Aptr += 8;
        float4 bv = *(const float4*)Bptr;  Bptr += (size_t)8 * N;
        As[0][a_col + 0][a_row] = av.x;
        As[0][a_col + 1][a_row] = av.y;
        As[0][a_col + 2][a_row] = av.z;
        As[0][a_col + 3][a_row] = av.w;
        *(float4*)&Bs[0][b_row][b_col] = bv;
    }
    __syncthreads();

    const int ntiles = K >> 3;
    int buf = 0;
    for (int t = 0; t < ntiles; ++t) {
        const bool has_next = (t + 1 < ntiles);
        float4 av2, bv2;
        if (has_next) {
            av2 = *(const float4*)Aptr;  Aptr += 8;
            bv2 = *(const float4*)Bptr;  Bptr += (size_t)8 * N;
        }

#pragma unroll
        for (int kk = 0; kk < 8; ++kk) {
            float4 a0 = *(const float4*)&As[buf][kk][tm];
            float4 a1 = *(const float4*)&As[buf][kk][tm + 4];
            float4 b0 = *(const float4*)&Bs[buf][kk][tn];
            float4 b1 = *(const float4*)&Bs[buf][kk][tn + 4];
            float ar[8] = {a0.x,a0.y,a0.z,a0.w,a1.x,a1.y,a1.z,a1.w};
            float br[8] = {b0.x,b0.y,b0.z,b0.w,b1.x,b1.y,b1.z,b1.w};
#pragma unroll
            for (int i = 0; i < 8; ++i)
#pragma unroll
                for (int j = 0; j < 8; ++j)
                    acc[i][j] = fmaf(ar[i], br[j], acc[i][j]);
        }

        if (has_next) {
            const int nb = buf ^ 1;
            As[nb][a_col + 0][a_row] = av2.x;
            As[nb][a_col + 1][a_row] = av2.y;
            As[nb][a_col + 2][a_row] = av2.z;
            As[nb][a_col + 3][a_row] = av2.w;
            *(float4*)&Bs[nb][b_row][b_col] = bv2;
        }
        __syncthreads();
        buf ^= 1;
    }

#pragma unroll
    for (int i = 0; i < 8; ++i) {
        float* Crow = C + (size_t)(bm + tm + i) * N + bn + tn;
        float4 c0 = {acc[i][0], acc[i][1], acc[i][2], acc[i][3]};
        float4 c1 = {acc[i][4], acc[i][5], acc[i][6], acc[i][7]};
        *(float4*)(Crow)     = c0;
        *(float4*)(Crow + 4) = c1;
    }
}

// ---------------------------------------------------------------------------
// RoPE + split + transpose: qkv[B,T,3C] -> q,k (roped) and v in [B,H,T,D]
// ---------------------------------------------------------------------------
__global__ void rope_split_k(const float* __restrict__ qkv,
                             float* __restrict__ q,
                             float* __restrict__ k,
                             float* __restrict__ v)
{
    const int idx = blockIdx.x * blockDim.x + threadIdx.x;  // B*T*H*32 total
    const int p = idx & 31;
    const int h = (idx >> 5) & 15;
    const int t = (idx >> 9) & 2047;
    const int b = idx >> 20;

    const float* base = qkv + (size_t)(b * T_ + t) * F3_;
    const int c = h * D_ + 2 * p;

    const float q1 = base[c],          q2 = base[c + 1];
    const float k1 = base[C_ + c],     k2 = base[C_ + c + 1];
    const float v1 = base[2*C_ + c],   v2 = base[2*C_ + c + 1];

    const float inv = exp2f(-(float)(2 * p) * (13.287712379549449f / 64.f));
    const float ang = (float)t * inv;
    float sn, cs;
    sincosf(ang, &sn, &cs);

    const size_t o = ((size_t)((b * H_ + h) * T_ + t)) * D_ + 2 * p;
    q[o]     = q1 * cs - q2 * sn;
    q[o + 1] = q1 * sn + q2 * cs;
    k[o]     = k1 * cs - k2 * sn;
    k[o + 1] = k1 * sn + k2 * cs;
    v[o]     = v1;
    v[o + 1] = v2;
}

// ---------------------------------------------------------------------------
// Causal flash attention, fp32, vectorized LDS.128 inner loops.
// Softmax runs in base-2 (scale folded with log2e); exp via FFMA-only fexp2.
// S-phase column mapping INTERLEAVED (col = tn + 16*j): per-lane K-row
// spacing 1 -> stride KPS=68 float4 loads are bank-conflict-free.
// P aliases the K buffer after S is computed.
// ---------------------------------------------------------------------------
#define KPS 68
#define ATT_SMEM ((64*64 + 64*KPS + 64*64) * 4)   // 50176 bytes

__global__ __launch_bounds__(256) void attn_k(
    const float* __restrict__ Q, const float* __restrict__ K,
    const float* __restrict__ V, float* __restrict__ Y)
{
    extern __shared__ float sm[];
    float* Qs = sm;               // [64][64]
    float* KP = sm + 64*64;       // [64][KPS]  (K tile, later P tile)
    float* Vs = KP + 64*KPS;      // [64][64]

    // Longest blocks (largest qt) first to shrink the wave tail.
    const int qt = (int)gridDim.x - 1 - (int)blockIdx.x;   // 0..31
    const int h  = blockIdx.y;
    const int b  = blockIdx.z;
    const int bh = b * H_ + h;

    const float* Qp = Q + (size_t)bh * T_ * D_;
    const float* Kp = K + (size_t)bh * T_ * D_;
    const float* Vp = V + (size_t)bh * T_ * D_;

    const int tid = threadIdx.x;
    const int tm = tid >> 4;      // 0..15
    const int tn = tid & 15;      // 0..15
    const int tm4 = tm * 4, tn4 = tn * 4;
    const int q0 = qt * 64;

    const int lr = tid >> 4;              // loader row within pass
    const int lc = (tid & 15) * 4;        // loader col (float4)

    // Load Q tile
#pragma unroll
    for (int ps = 0; ps < 4; ++ps) {
        int r = ps * 16 + lr;
        *(float4*)&Qs[r * 64 + lc] = *(const float4*)&Qp[(size_t)(q0 + r) * D_ + lc];
    }

    float m[4], l[4], o[4][4];
#pragma unroll
    for (int i = 0; i < 4; ++i) {
        m[i] = -INFINITY; l[i] = 0.f;
#pragma unroll
        for (int j = 0; j < 4; ++j) o[i][j] = 0.f;
    }

    for (int kt = 0; kt <= qt; ++kt) {
        const int k0 = kt * 64;
        __syncthreads();   // previous iteration done with KP(=P) and Vs

        // Load K (stride KPS) and V tiles
#pragma unroll
        for (int ps = 0; ps < 4; ++ps) {
            int r = ps * 16 + lr;
            *(float4*)&KP[r * KPS + lc] = *(const float4*)&Kp[(size_t)(k0 + r) * D_ + lc];
            *(float4*)&Vs[r * 64  + lc] = *(const float4*)&Vp[(size_t)(k0 + r) * D_ + lc];
        }
        __syncthreads();

        // S = Q @ K^T. s[i][j] is S[q0+tm4+i][k0 + tn + 16*j] (interleaved cols)
        float s[4][4];
#pragma unroll
        for (int i = 0; i < 4; ++i)
#pragma unroll
            for (int j = 0; j < 4; ++j) s[i][j] = 0.f;

#pragma unroll 4
        for (int d = 0; d < 64; d += 4) {
            float4 a0 = *(const float4*)&Qs[(tm4 + 0) * 64 + d];
            float4 a1 = *(const float4*)&Qs[(tm4 + 1) * 64 + d];
            float4 a2 = *(const float4*)&Qs[(tm4 + 2) * 64 + d];
            float4 a3 = *(const float4*)&Qs[(tm4 + 3) * 64 + d];
            float4 b0 = *(const float4*)&KP[(tn +  0) * KPS + d];
            float4 b1 = *(const float4*)&KP[(tn + 16) * KPS + d];
            float4 b2 = *(const float4*)&KP[(tn + 32) * KPS + d];
            float4 b3 = *(const float4*)&KP[(tn + 48) * KPS + d];
#define SDOT(i, A) \
            s[i][0] = fmaf(A.x,b0.x, fmaf(A.y,b0.y, fmaf(A.z,b0.z, fmaf(A.w,b0.w, s[i][0])))); \
            s[i][1] = fmaf(A.x,b1.x, fmaf(A.y,b1.y, fmaf(A.z,b1.z, fmaf(A.w,b1.w, s[i][1])))); \
            s[i][2] = fmaf(A.x,b2.x, fmaf(A.y,b2.y, fmaf(A.z,b2.z, fmaf(A.w,b2.w, s[i][2])))); \
            s[i][3] = fmaf(A.x,b3.x, fmaf(A.y,b3.y, fmaf(A.z,b3.z, fmaf(A.w,b3.w, s[i][3]))));
            SDOT(0, a0) SDOT(1, a1) SDOT(2, a2) SDOT(3, a3)
#undef SDOT
        }

        // Base-2 softmax: scale = (1/sqrt(64)) * log2(e)
        const float scale2 = 0.125f * 1.4426950408889634f;
#pragma unroll
        for (int i = 0; i < 4; ++i)
#pragma unroll
            for (int j = 0; j < 4; ++j) s[i][j] *= scale2;

        if (kt == qt) {   // diagonal tile: causal mask (col = k0 + tn + 16j)
#pragma unroll
            for (int i = 0; i < 4; ++i)
#pragma unroll
                for (int j = 0; j < 4; ++j)
                    if (k0 + tn + 16*j > q0 + tm4 + i) s[i][j] = -INFINITY;
        }

        // Row max over the 16 tn lanes
        float rmax[4];
#pragma unroll
        for (int i = 0; i < 4; ++i)
            rmax[i] = fmaxf(fmaxf(s[i][0], s[i][1]), fmaxf(s[i][2], s[i][3]));
#pragma unroll
        for (int off = 8; off >= 1; off >>= 1)
#pragma unroll
            for (int i = 0; i < 4; ++i)
                rmax[i] = fmaxf(rmax[i], __shfl_xor_sync(0xffffffffu, rmax[i], off));

        float alpha[4], rsum[4];
#pragma unroll
        for (int i = 0; i < 4; ++i) {
            float mn = fmaxf(m[i], rmax[i]);
            alpha[i] = fexp2(m[i] - mn);
            m[i] = mn;
            rsum[i] = 0.f;
#pragma unroll
            for (int j = 0; j < 4; ++j) {
                s[i][j] = fexp2(s[i][j] - mn);
                rsum[i] += s[i][j];
            }
        }
#pragma unroll
        for (int off = 8; off >= 1; off >>= 1)
#pragma unroll
            for (int i = 0; i < 4; ++i)
                rsum[i] += __shfl_xor_sync(0xffffffffu, rsum[i], off);

#pragma unroll
        for (int i = 0; i < 4; ++i) {
            l[i] = l[i] * alpha[i] + rsum[i];
#pragma unroll
            for (int j = 0; j < 4; ++j) o[i][j] *= alpha[i];
        }

        __syncthreads();   // everyone done reading KP as K
        // Scatter P into KP at interleaved columns (conflict-free: banks
        // (16*tm + tn) mod 32 all distinct within a warp)
#pragma unroll
        for (int i = 0; i < 4; ++i)
#pragma unroll
            for (int j = 0; j < 4; ++j)
                KP[(tm4 + i) * KPS + tn + 16*j] = s[i][j];
        __syncthreads();

        // O += P @ V  (P float4 reads are per-phase broadcasts; V float4
        // reads at tn4 hit distinct banks). Output cols contiguous tn4+j.
#pragma unroll 4
        for (int jj = 0; jj < 64; jj += 4) {
            float4 p0 = *(const float4*)&KP[(tm4 + 0) * KPS + jj];
            float4 p1 = *(const float4*)&KP[(tm4 + 1) * KPS + jj];
            float4 p2 = *(const float4*)&KP[(tm4 + 2) * KPS + jj];
            float4 p3 = *(const float4*)&KP[(tm4 + 3) * KPS + jj];
            float4 v0 = *(const float4*)&Vs[(jj + 0) * 64 + tn4];
            float4 v1 = *(const float4*)&Vs[(jj + 1) * 64 + tn4];
            float4 v2 = *(const float4*)&Vs[(jj + 2) * 64 + tn4];
            float4 v3 = *(const float4*)&Vs[(jj + 3) * 64 + tn4];
#define PDOT(i, P) \
            o[i][0] = fmaf(P.x,v0.x, fmaf(P.y,v1.x, fmaf(P.z,v2.x, fmaf(P.w,v3.x, o[i][0])))); \
            o[i][1] = fmaf(P.x,v0.y, fmaf(P.y,v1.y, fmaf(P.z,v2.y, fmaf(P.w,v3.y, o[i][1])))); \
            o[i][2] = fmaf(P.x,v0.z, fmaf(P.y,v1.z, fmaf(P.z,v2.z, fmaf(P.w,v3.z, o[i][2])))); \
            o[i][3] = fmaf(P.x,v0.w, fmaf(P.y,v1.w, fmaf(P.z,v2.w, fmaf(P.w,v3.w, o[i][3]))));
            PDOT(0, p0) PDOT(1, p1) PDOT(2, p2) PDOT(3, p3)
#undef PDOT
        }
    }

    // Epilogue: normalize, write y as [B,T,H,D] == [B,T,C]
#pragma unroll
    for (int i = 0; i < 4; ++i) {
        const float inv = 1.f / l[i];
        const int t = q0 + tm4 + i;
        float4 w = {o[i][0]*inv, o[i][1]*inv, o[i][2]*inv, o[i][3]*inv};
        *(float4*)(Y + ((size_t)(b * T_ + t) * H_ + h) * D_ + tn4) = w;
    }
}

// ---------------------------------------------------------------------------
extern "C" void kernel_launch(void* const* d_in, const int* in_sizes, int n_in,
                              void* d_out, int out_size)
{
    const float* x      = (const float*)d_in[0];   // [B,T,C]
    const float* W_attn = (const float*)d_in[1];   // [C,3C]
    const float* W_proj = (const float*)d_in[2];   // [C,C]
    float* out = (float*)d_out;                    // [B,T,C]

    float *qkv, *q, *k, *v, *y;
    cudaGetSymbolAddress((void**)&qkv, g_qkv);
    cudaGetSymbolAddress((void**)&q,   g_q);
    cudaGetSymbolAddress((void**)&k,   g_k);
    cudaGetSymbolAddress((void**)&v,   g_v);
    cudaGetSymbolAddress((void**)&y,   g_y);

    cudaFuncSetAttribute(attn_k, cudaFuncAttributeMaxDynamicSharedMemorySize, ATT_SMEM);

    // 1) QKV GEMM: [8192,1024] @ [1024,3072]
    {
        dim3 grid(F3_ / 128, BT_ / 128);
        sgemm_k<<<grid, 256>>>(x, W_attn, qkv, BT_, F3_, C_);
    }
    // 2) RoPE + split/transpose
    {
        int total = B_ * T_ * H_ * (D_ / 2);   // 4,194,304
        rope_split_k<<<total / 256, 256>>>(qkv, q, k, v);
    }
    // 3) Causal flash attention
    {
        dim3 grid(T_ / 64, H_, B_);
        attn_k<<<grid, 256, ATT_SMEM>>>(q, k, v, y);
    }
    // 4) Projection GEMM: [8192,1024] @ [1024,1024]
    {
        dim3 grid(C_ / 128, BT_ / 128);
        sgemm_k<<<grid, 256>>>(y, W_proj, out, BT_, C_, C_);
    }
}

// round 8
// speedup vs baseline: 1.3233x; 1.3233x over previous
#include <cuda_runtime.h>
#include <math.h>
#include <float.h>

// Problem constants
#define B_   4
#define T_   2048
#define C_   1024
#define H_   16
#define D_   64
#define BT_  (B_*T_)           // 8192
#define F3_  (3*C_)            // 3072

// Scratch (static device globals: alloc-free, graph-safe)
__device__ float g_qkv[(size_t)BT_ * F3_];        // [B*T, 3C]
__device__ float g_q[(size_t)B_*H_*T_*D_];        // [B,H,T,D]
__device__ float g_k[(size_t)B_*H_*T_*D_];
__device__ float g_v[(size_t)B_*H_*T_*D_];
__device__ float g_y[(size_t)BT_ * C_];           // [B,T,C]

// FFMA-only exp2 (keeps exp off any narrow pipe; deg-5, rel err ~2e-6)
__device__ __forceinline__ float fexp2(float x) {
    x = fmaxf(x, -126.f);
    float fl = rintf(x);
    float fr = x - fl;                  // in [-0.5, 0.5]
    float p = 0.0013333558f;
    p = fmaf(p, fr, 0.0096181291f);
    p = fmaf(p, fr, 0.0555041087f);
    p = fmaf(p, fr, 0.2402265069f);
    p = fmaf(p, fr, 0.6931471806f);
    p = fmaf(p, fr, 1.0f);
    return __int_as_float(__float_as_int(p) + (((int)fl) << 23));
}

__device__ __forceinline__ unsigned tf32cvt(float x) {
    unsigned r;
    asm("cvt.rna.tf32.f32 %0, %1;" : "=r"(r) : "f"(x));
    return r;
}

// D += A(16x8,row,tf32) * B(8x8,col,tf32)
__device__ __forceinline__ void mma_tf32(float* d, const unsigned* a, const unsigned* b) {
    asm volatile(
        "mma.sync.aligned.m16n8k8.row.col.f32.tf32.tf32.f32 "
        "{%0,%1,%2,%3}, {%4,%5,%6,%7}, {%8,%9}, {%0,%1,%2,%3};"
        : "+f"(d[0]), "+f"(d[1]), "+f"(d[2]), "+f"(d[3])
        : "r"(a[0]), "r"(a[1]), "r"(a[2]), "r"(a[3]), "r"(b[0]), "r"(b[1]));
}

// ---------------------------------------------------------------------------
// SGEMM: C[M,N] = A[M,K] @ B[K,N], fp32, 128x128xBK8, double-buffered.
// ---------------------------------------------------------------------------
__global__ __launch_bounds__(256) void sgemm_k(
    const float* __restrict__ A, const float* __restrict__ B,
    float* __restrict__ C, int M, int N, int K)
{
    __shared__ float As[2][8][128];
    __shared__ float Bs[2][8][128];

    const int tid = threadIdx.x;
    const int bm = blockIdx.y * 128;
    const int bn = blockIdx.x * 128;

    const int a_row = tid >> 1;
    const int a_col = (tid & 1) * 4;
    const int b_row = tid >> 5;
    const int b_col = (tid & 31) * 4;

    const float* Aptr = A + (size_t)(bm + a_row) * K + a_col;
    const float* Bptr = B + (size_t)b_row * N + bn + b_col;

    const int tm = (tid >> 4) * 8;
    const int tn = (tid & 15) * 8;

    float acc[8][8];
#pragma unroll
    for (int i = 0; i < 8; ++i)
#pragma unroll
        for (int j = 0; j < 8; ++j) acc[i][j] = 0.f;

    {
        float4 av = *(const float4*)Aptr;  Aptr += 8;
        float4 bv = *(const float4*)Bptr;  Bptr += (size_t)8 * N;
        As[0][a_col + 0][a_row] = av.x;
        As[0][a_col + 1][a_row] = av.y;
        As[0][a_col + 2][a_row] = av.z;
        As[0][a_col + 3][a_row] = av.w;
        *(float4*)&Bs[0][b_row][b_col] = bv;
    }
    __syncthreads();

    const int ntiles = K >> 3;
    int buf = 0;
    for (int t = 0; t < ntiles; ++t) {
        const bool has_next = (t + 1 < ntiles);
        float4 av2, bv2;
        if (has_next) {
            av2 = *(const float4*)Aptr;  Aptr += 8;
            bv2 = *(const float4*)Bptr;  Bptr += (size_t)8 * N;
        }

#pragma unroll
        for (int kk = 0; kk < 8; ++kk) {
            float4 a0 = *(const float4*)&As[buf][kk][tm];
            float4 a1 = *(const float4*)&As[buf][kk][tm + 4];
            float4 b0 = *(const float4*)&Bs[buf][kk][tn];
            float4 b1 = *(const float4*)&Bs[buf][kk][tn + 4];
            float ar[8] = {a0.x,a0.y,a0.z,a0.w,a1.x,a1.y,a1.z,a1.w};
            float br[8] = {b0.x,b0.y,b0.z,b0.w,b1.x,b1.y,b1.z,b1.w};
#pragma unroll
            for (int i = 0; i < 8; ++i)
#pragma unroll
                for (int j = 0; j < 8; ++j)
                    acc[i][j] = fmaf(ar[i], br[j], acc[i][j]);
        }

        if (has_next) {
            const int nb = buf ^ 1;
            As[nb][a_col + 0][a_row] = av2.x;
            As[nb][a_col + 1][a_row] = av2.y;
            As[nb][a_col + 2][a_row] = av2.z;
            As[nb][a_col + 3][a_row] = av2.w;
            *(float4*)&Bs[nb][b_row][b_col] = bv2;
        }
        __syncthreads();
        buf ^= 1;
    }

#pragma unroll
    for (int i = 0; i < 8; ++i) {
        float* Crow = C + (size_t)(bm + tm + i) * N + bn + tn;
        float4 c0 = {acc[i][0], acc[i][1], acc[i][2], acc[i][3]};
        float4 c1 = {acc[i][4], acc[i][5], acc[i][6], acc[i][7]};
        *(float4*)(Crow)     = c0;
        *(float4*)(Crow + 4) = c1;
    }
}

// ---------------------------------------------------------------------------
// RoPE + split + transpose: qkv[B,T,3C] -> q,k (roped) and v in [B,H,T,D]
// ---------------------------------------------------------------------------
__global__ void rope_split_k(const float* __restrict__ qkv,
                             float* __restrict__ q,
                             float* __restrict__ k,
                             float* __restrict__ v)
{
    const int idx = blockIdx.x * blockDim.x + threadIdx.x;
    const int p = idx & 31;
    const int h = (idx >> 5) & 15;
    const int t = (idx >> 9) & 2047;
    const int b = idx >> 20;

    const float* base = qkv + (size_t)(b * T_ + t) * F3_;
    const int c = h * D_ + 2 * p;

    const float q1 = base[c],          q2 = base[c + 1];
    const float k1 = base[C_ + c],     k2 = base[C_ + c + 1];
    const float v1 = base[2*C_ + c],   v2 = base[2*C_ + c + 1];

    const float inv = exp2f(-(float)(2 * p) * (13.287712379549449f / 64.f));
    const float ang = (float)t * inv;
    float sn, cs;
    sincosf(ang, &sn, &cs);

    const size_t o = ((size_t)((b * H_ + h) * T_ + t)) * D_ + 2 * p;
    q[o]     = q1 * cs - q2 * sn;
    q[o + 1] = q1 * sn + q2 * cs;
    k[o]     = k1 * cs - k2 * sn;
    k[o + 1] = k1 * sn + k2 * cs;
    v[o]     = v1;
    v[o + 1] = v2;
}

// ---------------------------------------------------------------------------
// Tensor-core causal flash attention (tf32 mma.sync.m16n8k8).
// Block: 256 thr / 8 warps; q-tile 128 rows (warp w owns rows 16w..16w+15,
// ALL 64 k-cols -> softmax is warp-private, no cross-warp reduction).
// K-tile 64. Q frags hoisted to registers; Q staging smem reused as P buffer
// (P written+read by the same warp; __syncwarp only).
// Strides: Q/P/K = 76 (12*row+col banks, conflict-free frags),
//          V = 72 (8k+n banks, conflict-free).
// ---------------------------------------------------------------------------
#define SQP 76
#define SKK 76
#define SVV 72
#define ATT_SMEM ((128*SQP + 64*SKK + 64*SVV) * 4)   // 76800 bytes

__global__ __launch_bounds__(256) void attn_k(
    const float* __restrict__ Q, const float* __restrict__ K,
    const float* __restrict__ V, float* __restrict__ Y)
{
    extern __shared__ float sm[];
    float* QP = sm;                 // [128][SQP]  Q staging, then P
    float* Ks = sm + 128*SQP;       // [64][SKK]   tf32 bits
    float* Vs = Ks + 64*SKK;        // [64][SVV]   tf32 bits

    const int qb = (int)gridDim.x - 1 - (int)blockIdx.x;  // largest first
    const int h  = blockIdx.y;
    const int b  = blockIdx.z;
    const int bh = b * H_ + h;
    const int q0 = qb * 128;

    const float* Qg = Q + (size_t)bh * T_ * D_;
    const float* Kg = K + (size_t)bh * T_ * D_;
    const float* Vg = V + (size_t)bh * T_ * D_;

    const int tid  = threadIdx.x;
    const int warp = tid >> 5;
    const int lane = tid & 31;
    const int grp  = lane >> 2;      // 0..7
    const int tig  = lane & 3;       // 0..3

    // Stage Q tile (128x64) into QP
#pragma unroll
    for (int i = 0; i < 8; ++i) {
        int idx = tid + 256 * i;
        int row = idx >> 4;
        int c4  = (idx & 15) * 4;
        *(float4*)&QP[row * SQP + c4] = *(const float4*)&Qg[(size_t)(q0 + row) * D_ + c4];
    }
    __syncthreads();

    // Hoist Q A-fragments (scale folded: 1/8 * log2(e)), tf32
    const float scale2 = 0.125f * 1.4426950408889634f;
    unsigned qa[8][4];
    {
        const int r0 = 16 * warp + grp;
#pragma unroll
        for (int ks = 0; ks < 8; ++ks) {
            int cbase = ks * 8 + tig;
            qa[ks][0] = tf32cvt(QP[r0 * SQP + cbase] * scale2);
            qa[ks][1] = tf32cvt(QP[(r0 + 8) * SQP + cbase] * scale2);
            qa[ks][2] = tf32cvt(QP[r0 * SQP + cbase + 4] * scale2);
            qa[ks][3] = tf32cvt(QP[(r0 + 8) * SQP + cbase + 4] * scale2);
        }
    }

    float m0 = -INFINITY, m1 = -INFINITY, l0 = 0.f, l1 = 0.f;
    float oa[8][4];
#pragma unroll
    for (int nt = 0; nt < 8; ++nt)
#pragma unroll
        for (int j = 0; j < 4; ++j) oa[nt][j] = 0.f;

    const int nk = 2 * qb + 2;              // 64-wide k tiles
    const int rwarp0 = q0 + 16 * warp;      // warp's first global row

    for (int kt = 0; kt < nk; ++kt) {
        const int k0 = kt * 64;
        __syncthreads();   // prev iter done with Ks/Vs (and Q extraction done)

        // Load K,V tiles, converting to tf32 at store
#pragma unroll
        for (int i = 0; i < 4; ++i) {
            int idx = tid + 256 * i;
            int row = idx >> 4;
            int c4  = (idx & 15) * 4;
            float4 kv = *(const float4*)&Kg[(size_t)(k0 + row) * D_ + c4];
            float4 vv = *(const float4*)&Vg[(size_t)(k0 + row) * D_ + c4];
            float* kd = &Ks[row * SKK + c4];
            kd[0] = __uint_as_float(tf32cvt(kv.x));
            kd[1] = __uint_as_float(tf32cvt(kv.y));
            kd[2] = __uint_as_float(tf32cvt(kv.z));
            kd[3] = __uint_as_float(tf32cvt(kv.w));
            float* vd = &Vs[row * SVV + c4];
            vd[0] = __uint_as_float(tf32cvt(vv.x));
            vd[1] = __uint_as_float(tf32cvt(vv.y));
            vd[2] = __uint_as_float(tf32cvt(vv.z));
            vd[3] = __uint_as_float(tf32cvt(vv.w));
        }
        __syncthreads();

        // S = (Q*scale) @ K^T : per warp 16x64 via 8 n-tiles x 8 k-steps
        float s[8][4];
#pragma unroll
        for (int nt = 0; nt < 8; ++nt)
#pragma unroll
            for (int j = 0; j < 4; ++j) s[nt][j] = 0.f;

#pragma unroll
        for (int ks = 0; ks < 8; ++ks) {
#pragma unroll
            for (int nt = 0; nt < 8; ++nt) {
                int naddr = (nt * 8 + grp) * SKK + ks * 8 + tig;
                unsigned bfr[2];
                bfr[0] = __float_as_uint(Ks[naddr]);
                bfr[1] = __float_as_uint(Ks[naddr + 4]);
                mma_tf32(s[nt], qa[ks], bfr);
            }
        }

        // Causal mask. Needed whenever the tile's max col exceeds this
        // warp's MIN row (rwarp0) — fixed from rwarp0+15, which skipped
        // the partially-masked case for high warps on the last tile.
        if (k0 + 63 > rwarp0) {
            const int r0g = rwarp0 + grp;
#pragma unroll
            for (int nt = 0; nt < 8; ++nt) {
                int cb = k0 + nt * 8 + 2 * tig;
                if (cb     > r0g)     s[nt][0] = -INFINITY;
                if (cb + 1 > r0g)     s[nt][1] = -INFINITY;
                if (cb     > r0g + 8) s[nt][2] = -INFINITY;
                if (cb + 1 > r0g + 8) s[nt][3] = -INFINITY;
            }
        }

        // Warp-private online softmax (rows r0=rwarp0+grp, r1=+8)
        float rm0 = -INFINITY, rm1 = -INFINITY;
#pragma unroll
        for (int nt = 0; nt < 8; ++nt) {
            rm0 = fmaxf(rm0, fmaxf(s[nt][0], s[nt][1]));
            rm1 = fmaxf(rm1, fmaxf(s[nt][2], s[nt][3]));
        }
        rm0 = fmaxf(rm0, __shfl_xor_sync(0xffffffffu, rm0, 1));
        rm0 = fmaxf(rm0, __shfl_xor_sync(0xffffffffu, rm0, 2));
        rm1 = fmaxf(rm1, __shfl_xor_sync(0xffffffffu, rm1, 1));
        rm1 = fmaxf(rm1, __shfl_xor_sync(0xffffffffu, rm1, 2));

        float mn0 = fmaxf(m0, rm0), mn1 = fmaxf(m1, rm1);
        float al0 = fexp2(m0 - mn0), al1 = fexp2(m1 - mn1);
        m0 = mn0; m1 = mn1;

        float rs0 = 0.f, rs1 = 0.f;
#pragma unroll
        for (int nt = 0; nt < 8; ++nt) {
            s[nt][0] = fexp2(s[nt][0] - mn0);
            s[nt][1] = fexp2(s[nt][1] - mn0);
            s[nt][2] = fexp2(s[nt][2] - mn1);
            s[nt][3] = fexp2(s[nt][3] - mn1);
            rs0 += s[nt][0] + s[nt][1];
            rs1 += s[nt][2] + s[nt][3];
        }
        rs0 += __shfl_xor_sync(0xffffffffu, rs0, 1);
        rs0 += __shfl_xor_sync(0xffffffffu, rs0, 2);
        rs1 += __shfl_xor_sync(0xffffffffu, rs1, 1);
        rs1 += __shfl_xor_sync(0xffffffffu, rs1, 2);

        l0 = l0 * al0 + rs0;
        l1 = l1 * al1 + rs1;
#pragma unroll
        for (int nt = 0; nt < 8; ++nt) {
            oa[nt][0] *= al0; oa[nt][1] *= al0;
            oa[nt][2] *= al1; oa[nt][3] *= al1;
        }

        // Write P (tf32 bits) into QP — warp-private rows, so syncwarp only
        {
            const int pr0 = 16 * warp + grp;
#pragma unroll
            for (int nt = 0; nt < 8; ++nt) {
                int cb = nt * 8 + 2 * tig;
                float2 w0 = { __uint_as_float(tf32cvt(s[nt][0])),
                              __uint_as_float(tf32cvt(s[nt][1])) };
                float2 w1 = { __uint_as_float(tf32cvt(s[nt][2])),
                              __uint_as_float(tf32cvt(s[nt][3])) };
                *(float2*)&QP[pr0 * SQP + cb]       = w0;
                *(float2*)&QP[(pr0 + 8) * SQP + cb] = w1;
            }
        }
        __syncwarp();

        // O += P @ V : per warp 16x64, contract k=64 (8 k-steps)
#pragma unroll
        for (int ks = 0; ks < 8; ++ks) {
            const int pb = (16 * warp + grp) * SQP + ks * 8 + tig;
            unsigned pa[4];
            pa[0] = __float_as_uint(QP[pb]);
            pa[1] = __float_as_uint(QP[pb + 8 * SQP]);
            pa[2] = __float_as_uint(QP[pb + 4]);
            pa[3] = __float_as_uint(QP[pb + 8 * SQP + 4]);
#pragma unroll
            for (int nt = 0; nt < 8; ++nt) {
                int vaddr = (ks * 8 + tig) * SVV + nt * 8 + grp;
                unsigned bfr[2];
                bfr[0] = __float_as_uint(Vs[vaddr]);
                bfr[1] = __float_as_uint(Vs[vaddr + 4 * SVV]);
                mma_tf32(oa[nt], pa, bfr);
            }
        }
    }

    // Epilogue: normalize, write y as [B,T,H,D] == [B,T,C]
    const float i0 = 1.f / l0, i1 = 1.f / l1;
    const int t0 = rwarp0 + grp;
#pragma unroll
    for (int nt = 0; nt < 8; ++nt) {
        int d = nt * 8 + 2 * tig;
        float2 w0 = { oa[nt][0] * i0, oa[nt][1] * i0 };
        float2 w1 = { oa[nt][2] * i1, oa[nt][3] * i1 };
        *(float2*)(Y + ((size_t)(b * T_ + t0)     * H_ + h) * D_ + d) = w0;
        *(float2*)(Y + ((size_t)(b * T_ + t0 + 8) * H_ + h) * D_ + d) = w1;
    }
}

// ---------------------------------------------------------------------------
extern "C" void kernel_launch(void* const* d_in, const int* in_sizes, int n_in,
                              void* d_out, int out_size)
{
    const float* x      = (const float*)d_in[0];   // [B,T,C]
    const float* W_attn = (const float*)d_in[1];   // [C,3C]
    const float* W_proj = (const float*)d_in[2];   // [C,C]
    float* out = (float*)d_out;                    // [B,T,C]

    float *qkv, *q, *k, *v, *y;
    cudaGetSymbolAddress((void**)&qkv, g_qkv);
    cudaGetSymbolAddress((void**)&q,   g_q);
    cudaGetSymbolAddress((void**)&k,   g_k);
    cudaGetSymbolAddress((void**)&v,   g_v);
    cudaGetSymbolAddress((void**)&y,   g_y);

    cudaFuncSetAttribute(attn_k, cudaFuncAttributeMaxDynamicSharedMemorySize, ATT_SMEM);

    // 1) QKV GEMM: [8192,1024] @ [1024,3072]
    {
        dim3 grid(F3_ / 128, BT_ / 128);
        sgemm_k<<<grid, 256>>>(x, W_attn, qkv, BT_, F3_, C_);
    }
    // 2) RoPE + split/transpose
    {
        int total = B_ * T_ * H_ * (D_ / 2);
        rope_split_k<<<total / 256, 256>>>(qkv, q, k, v);
    }
    // 3) Tensor-core causal flash attention (q-tile 128)
    {
        dim3 grid(T_ / 128, H_, B_);
        attn_k<<<grid, 256, ATT_SMEM>>>(q, k, v, y);
    }
    // 4) Projection GEMM: [8192,1024] @ [1024,1024]
    {
        dim3 grid(C_ / 128, BT_ / 128);
        sgemm_k<<<grid, 256>>>(y, W_proj, out, BT_, C_, C_);
    }
}

// round 9
// speedup vs baseline: 2.3965x; 1.8111x over previous
#include <cuda_runtime.h>
#include <math.h>
#include <float.h>

// Problem constants
#define B_   4
#define T_   2048
#define C_   1024
#define H_   16
#define D_   64
#define BT_  (B_*T_)           // 8192
#define F3_  (3*C_)            // 3072

// Scratch (static device globals: alloc-free, graph-safe)
__device__ float g_qkv[(size_t)BT_ * F3_];        // [B*T, 3C]
__device__ float g_q[(size_t)B_*H_*T_*D_];        // [B,H,T,D]
__device__ float g_k[(size_t)B_*H_*T_*D_];
__device__ float g_v[(size_t)B_*H_*T_*D_];
__device__ float g_y[(size_t)BT_ * C_];           // [B,T,C]

// FFMA-only exp2 (deg-5, rel err ~2e-6)
__device__ __forceinline__ float fexp2(float x) {
    x = fmaxf(x, -126.f);
    float fl = rintf(x);
    float fr = x - fl;                  // in [-0.5, 0.5]
    float p = 0.0013333558f;
    p = fmaf(p, fr, 0.0096181291f);
    p = fmaf(p, fr, 0.0555041087f);
    p = fmaf(p, fr, 0.2402265069f);
    p = fmaf(p, fr, 0.6931471806f);
    p = fmaf(p, fr, 1.0f);
    return __int_as_float(__float_as_int(p) + (((int)fl) << 23));
}

__device__ __forceinline__ unsigned tf32cvt(float x) {
    unsigned r;
    asm("cvt.rna.tf32.f32 %0, %1;" : "=r"(r) : "f"(x));
    return r;
}

// D += A(16x8,row,tf32) * B(8x8,col,tf32)
__device__ __forceinline__ void mma_tf32(float* d, const unsigned* a, const unsigned* b) {
    asm volatile(
        "mma.sync.aligned.m16n8k8.row.col.f32.tf32.tf32.f32 "
        "{%0,%1,%2,%3}, {%4,%5,%6,%7}, {%8,%9}, {%0,%1,%2,%3};"
        : "+f"(d[0]), "+f"(d[1]), "+f"(d[2]), "+f"(d[3])
        : "r"(a[0]), "r"(a[1]), "r"(a[2]), "r"(a[3]), "r"(b[0]), "r"(b[1]));
}

// ---------------------------------------------------------------------------
// tf32 tensor-core GEMM: C[M,N] = A[M,K] @ B[K,N], fp32 in/out, tf32 mma.
// 128x128 tile, BK=16, 256 thr / 8 warps as 2x4 (warp tile 64x32).
// Double-buffered smem; cvt.rna at STS. Strides: A=20 (frag banks 4*grp
// pattern, conflict-free), B=136 (= 8 mod 32, 8*tig+grp covers all banks).
// ---------------------------------------------------------------------------
__global__ __launch_bounds__(256) void tf32gemm_k(
    const float* __restrict__ A, const float* __restrict__ B,
    float* __restrict__ C, int M, int N, int K)
{
    __shared__ float As[2][128][20];
    __shared__ float Bs[2][16][136];

    const int tid = threadIdx.x;
    const int bm = blockIdx.y * 128;
    const int bn = blockIdx.x * 128;

    const int warp = tid >> 5;
    const int lane = tid & 31;
    const int grp  = lane >> 2;          // 0..7
    const int tig  = lane & 3;           // 0..3
    const int m0   = (warp >> 2) * 64;   // 0 / 64
    const int n0   = (warp & 3) * 32;    // 0..96

    const int a_row = tid >> 1;          // 0..127
    const int a_col = (tid & 1) * 8;     // 0 / 8
    const int b_row = tid >> 4;          // 0..15
    const int b_col = (tid & 15) * 8;    // 0..120

    const float* Aptr = A + (size_t)(bm + a_row) * K + a_col;
    const float* Bptr = B + (size_t)b_row * N + bn + b_col;

    float acc[4][4][4];
#pragma unroll
    for (int mt = 0; mt < 4; ++mt)
#pragma unroll
        for (int nt = 0; nt < 4; ++nt)
#pragma unroll
            for (int j = 0; j < 4; ++j) acc[mt][nt][j] = 0.f;

    // Preload tile 0 (cvt to tf32 at store)
    {
        float4 a0 = *(const float4*)Aptr;
        float4 a1 = *(const float4*)(Aptr + 4);
        float4 b0 = *(const float4*)Bptr;
        float4 b1 = *(const float4*)(Bptr + 4);
        Aptr += 16;  Bptr += (size_t)16 * N;
        float* ad = &As[0][a_row][a_col];
        ad[0]=__uint_as_float(tf32cvt(a0.x)); ad[1]=__uint_as_float(tf32cvt(a0.y));
        ad[2]=__uint_as_float(tf32cvt(a0.z)); ad[3]=__uint_as_float(tf32cvt(a0.w));
        ad[4]=__uint_as_float(tf32cvt(a1.x)); ad[5]=__uint_as_float(tf32cvt(a1.y));
        ad[6]=__uint_as_float(tf32cvt(a1.z)); ad[7]=__uint_as_float(tf32cvt(a1.w));
        float* bd = &Bs[0][b_row][b_col];
        bd[0]=__uint_as_float(tf32cvt(b0.x)); bd[1]=__uint_as_float(tf32cvt(b0.y));
        bd[2]=__uint_as_float(tf32cvt(b0.z)); bd[3]=__uint_as_float(tf32cvt(b0.w));
        bd[4]=__uint_as_float(tf32cvt(b1.x)); bd[5]=__uint_as_float(tf32cvt(b1.y));
        bd[6]=__uint_as_float(tf32cvt(b1.z)); bd[7]=__uint_as_float(tf32cvt(b1.w));
    }
    __syncthreads();

    const int ntiles = K >> 4;
    int buf = 0;
    for (int t = 0; t < ntiles; ++t) {
        const bool has_next = (t + 1 < ntiles);
        float4 a0n, a1n, b0n, b1n;
        if (has_next) {
            a0n = *(const float4*)Aptr;
            a1n = *(const float4*)(Aptr + 4);
            b0n = *(const float4*)Bptr;
            b1n = *(const float4*)(Bptr + 4);
            Aptr += 16;  Bptr += (size_t)16 * N;
        }

#pragma unroll
        for (int kk = 0; kk < 2; ++kk) {
            unsigned bf[4][2];
#pragma unroll
            for (int nt = 0; nt < 4; ++nt) {
                bf[nt][0] = __float_as_uint(Bs[buf][kk*8 + tig    ][n0 + nt*8 + grp]);
                bf[nt][1] = __float_as_uint(Bs[buf][kk*8 + tig + 4][n0 + nt*8 + grp]);
            }
#pragma unroll
            for (int mt = 0; mt < 4; ++mt) {
                const int r = m0 + mt*16 + grp;
                unsigned af[4];
                af[0] = __float_as_uint(As[buf][r    ][kk*8 + tig]);
                af[1] = __float_as_uint(As[buf][r + 8][kk*8 + tig]);
                af[2] = __float_as_uint(As[buf][r    ][kk*8 + tig + 4]);
                af[3] = __float_as_uint(As[buf][r + 8][kk*8 + tig + 4]);
#pragma unroll
                for (int nt = 0; nt < 4; ++nt)
                    mma_tf32(acc[mt][nt], af, bf[nt]);
            }
        }

        if (has_next) {
            const int nb = buf ^ 1;
            float* ad = &As[nb][a_row][a_col];
            ad[0]=__uint_as_float(tf32cvt(a0n.x)); ad[1]=__uint_as_float(tf32cvt(a0n.y));
            ad[2]=__uint_as_float(tf32cvt(a0n.z)); ad[3]=__uint_as_float(tf32cvt(a0n.w));
            ad[4]=__uint_as_float(tf32cvt(a1n.x)); ad[5]=__uint_as_float(tf32cvt(a1n.y));
            ad[6]=__uint_as_float(tf32cvt(a1n.z)); ad[7]=__uint_as_float(tf32cvt(a1n.w));
            float* bd = &Bs[nb][b_row][b_col];
            bd[0]=__uint_as_float(tf32cvt(b0n.x)); bd[1]=__uint_as_float(tf32cvt(b0n.y));
            bd[2]=__uint_as_float(tf32cvt(b0n.z)); bd[3]=__uint_as_float(tf32cvt(b0n.w));
            bd[4]=__uint_as_float(tf32cvt(b1n.x)); bd[5]=__uint_as_float(tf32cvt(b1n.y));
            bd[6]=__uint_as_float(tf32cvt(b1n.z)); bd[7]=__uint_as_float(tf32cvt(b1n.w));
        }
        __syncthreads();
        buf ^= 1;
    }

    // Epilogue
#pragma unroll
    for (int mt = 0; mt < 4; ++mt) {
        const int row = bm + m0 + mt*16 + grp;
#pragma unroll
        for (int nt = 0; nt < 4; ++nt) {
            const int col = bn + n0 + nt*8 + 2*tig;
            float2 w0 = { acc[mt][nt][0], acc[mt][nt][1] };
            float2 w1 = { acc[mt][nt][2], acc[mt][nt][3] };
            *(float2*)&C[(size_t)row * N + col]       = w0;
            *(float2*)&C[(size_t)(row + 8) * N + col] = w1;
        }
    }
}

// ---------------------------------------------------------------------------
// RoPE + split + transpose: qkv[B,T,3C] -> q,k (roped) and v in [B,H,T,D]
// ---------------------------------------------------------------------------
__global__ void rope_split_k(const float* __restrict__ qkv,
                             float* __restrict__ q,
                             float* __restrict__ k,
                             float* __restrict__ v)
{
    const int idx = blockIdx.x * blockDim.x + threadIdx.x;
    const int p = idx & 31;
    const int h = (idx >> 5) & 15;
    const int t = (idx >> 9) & 2047;
    const int b = idx >> 20;

    const float* base = qkv + (size_t)(b * T_ + t) * F3_;
    const int c = h * D_ + 2 * p;

    const float q1 = base[c],          q2 = base[c + 1];
    const float k1 = base[C_ + c],     k2 = base[C_ + c + 1];
    const float v1 = base[2*C_ + c],   v2 = base[2*C_ + c + 1];

    const float inv = exp2f(-(float)(2 * p) * (13.287712379549449f / 64.f));
    const float ang = (float)t * inv;
    float sn, cs;
    sincosf(ang, &sn, &cs);

    const size_t o = ((size_t)((b * H_ + h) * T_ + t)) * D_ + 2 * p;
    q[o]     = q1 * cs - q2 * sn;
    q[o + 1] = q1 * sn + q2 * cs;
    k[o]     = k1 * cs - k2 * sn;
    k[o + 1] = k1 * sn + k2 * cs;
    v[o]     = v1;
    v[o + 1] = v2;
}

// ---------------------------------------------------------------------------
// Tensor-core causal flash attention (tf32 mma.sync.m16n8k8). Unchanged
// from R8 (passing): q-tile 128, warp-private softmax, P aliases Q smem.
// ---------------------------------------------------------------------------
#define SQP 76
#define SKK 76
#define SVV 72
#define ATT_SMEM ((128*SQP + 64*SKK + 64*SVV) * 4)   // 76800 bytes

__global__ __launch_bounds__(256) void attn_k(
    const float* __restrict__ Q, const float* __restrict__ K,
    const float* __restrict__ V, float* __restrict__ Y)
{
    extern __shared__ float sm[];
    float* QP = sm;                 // [128][SQP]  Q staging, then P
    float* Ks = sm + 128*SQP;       // [64][SKK]   tf32 bits
    float* Vs = Ks + 64*SKK;        // [64][SVV]   tf32 bits

    const int qb = (int)gridDim.x - 1 - (int)blockIdx.x;  // largest first
    const int h  = blockIdx.y;
    const int b  = blockIdx.z;
    const int bh = b * H_ + h;
    const int q0 = qb * 128;

    const float* Qg = Q + (size_t)bh * T_ * D_;
    const float* Kg = K + (size_t)bh * T_ * D_;
    const float* Vg = V + (size_t)bh * T_ * D_;

    const int tid  = threadIdx.x;
    const int warp = tid >> 5;
    const int lane = tid & 31;
    const int grp  = lane >> 2;      // 0..7
    const int tig  = lane & 3;       // 0..3

    // Stage Q tile (128x64) into QP
#pragma unroll
    for (int i = 0; i < 8; ++i) {
        int idx = tid + 256 * i;
        int row = idx >> 4;
        int c4  = (idx & 15) * 4;
        *(float4*)&QP[row * SQP + c4] = *(const float4*)&Qg[(size_t)(q0 + row) * D_ + c4];
    }
    __syncthreads();

    // Hoist Q A-fragments (scale folded: 1/8 * log2(e)), tf32
    const float scale2 = 0.125f * 1.4426950408889634f;
    unsigned qa[8][4];
    {
        const int r0 = 16 * warp + grp;
#pragma unroll
        for (int ks = 0; ks < 8; ++ks) {
            int cbase = ks * 8 + tig;
            qa[ks][0] = tf32cvt(QP[r0 * SQP + cbase] * scale2);
            qa[ks][1] = tf32cvt(QP[(r0 + 8) * SQP + cbase] * scale2);
            qa[ks][2] = tf32cvt(QP[r0 * SQP + cbase + 4] * scale2);
            qa[ks][3] = tf32cvt(QP[(r0 + 8) * SQP + cbase + 4] * scale2);
        }
    }

    float m0 = -INFINITY, m1 = -INFINITY, l0 = 0.f, l1 = 0.f;
    float oa[8][4];
#pragma unroll
    for (int nt = 0; nt < 8; ++nt)
#pragma unroll
        for (int j = 0; j < 4; ++j) oa[nt][j] = 0.f;

    const int nk = 2 * qb + 2;              // 64-wide k tiles
    const int rwarp0 = q0 + 16 * warp;      // warp's first global row

    for (int kt = 0; kt < nk; ++kt) {
        const int k0 = kt * 64;
        __syncthreads();

        // Load K,V tiles, converting to tf32 at store
#pragma unroll
        for (int i = 0; i < 4; ++i) {
            int idx = tid + 256 * i;
            int row = idx >> 4;
            int c4  = (idx & 15) * 4;
            float4 kv = *(const float4*)&Kg[(size_t)(k0 + row) * D_ + c4];
            float4 vv = *(const float4*)&Vg[(size_t)(k0 + row) * D_ + c4];
            float* kd = &Ks[row * SKK + c4];
            kd[0] = __uint_as_float(tf32cvt(kv.x));
            kd[1] = __uint_as_float(tf32cvt(kv.y));
            kd[2] = __uint_as_float(tf32cvt(kv.z));
            kd[3] = __uint_as_float(tf32cvt(kv.w));
            float* vd = &Vs[row * SVV + c4];
            vd[0] = __uint_as_float(tf32cvt(vv.x));
            vd[1] = __uint_as_float(tf32cvt(vv.y));
            vd[2] = __uint_as_float(tf32cvt(vv.z));
            vd[3] = __uint_as_float(tf32cvt(vv.w));
        }
        __syncthreads();

        // S = (Q*scale) @ K^T
        float s[8][4];
#pragma unroll
        for (int nt = 0; nt < 8; ++nt)
#pragma unroll
            for (int j = 0; j < 4; ++j) s[nt][j] = 0.f;

#pragma unroll
        for (int ks = 0; ks < 8; ++ks) {
#pragma unroll
            for (int nt = 0; nt < 8; ++nt) {
                int naddr = (nt * 8 + grp) * SKK + ks * 8 + tig;
                unsigned bfr[2];
                bfr[0] = __float_as_uint(Ks[naddr]);
                bfr[1] = __float_as_uint(Ks[naddr + 4]);
                mma_tf32(s[nt], qa[ks], bfr);
            }
        }

        // Causal mask (gate on warp's MIN row)
        if (k0 + 63 > rwarp0) {
            const int r0g = rwarp0 + grp;
#pragma unroll
            for (int nt = 0; nt < 8; ++nt) {
                int cb = k0 + nt * 8 + 2 * tig;
                if (cb     > r0g)     s[nt][0] = -INFINITY;
                if (cb + 1 > r0g)     s[nt][1] = -INFINITY;
                if (cb     > r0g + 8) s[nt][2] = -INFINITY;
                if (cb + 1 > r0g + 8) s[nt][3] = -INFINITY;
            }
        }

        // Warp-private online softmax
        float rm0 = -INFINITY, rm1 = -INFINITY;
#pragma unroll
        for (int nt = 0; nt < 8; ++nt) {
            rm0 = fmaxf(rm0, fmaxf(s[nt][0], s[nt][1]));
            rm1 = fmaxf(rm1, fmaxf(s[nt][2], s[nt][3]));
        }
        rm0 = fmaxf(rm0, __shfl_xor_sync(0xffffffffu, rm0, 1));
        rm0 = fmaxf(rm0, __shfl_xor_sync(0xffffffffu, rm0, 2));
        rm1 = fmaxf(rm1, __shfl_xor_sync(0xffffffffu, rm1, 1));
        rm1 = fmaxf(rm1, __shfl_xor_sync(0xffffffffu, rm1, 2));

        float mn0 = fmaxf(m0, rm0), mn1 = fmaxf(m1, rm1);
        float al0 = fexp2(m0 - mn0), al1 = fexp2(m1 - mn1);
        m0 = mn0; m1 = mn1;

        float rs0 = 0.f, rs1 = 0.f;
#pragma unroll
        for (int nt = 0; nt < 8; ++nt) {
            s[nt][0] = fexp2(s[nt][0] - mn0);
            s[nt][1] = fexp2(s[nt][1] - mn0);
            s[nt][2] = fexp2(s[nt][2] - mn1);
            s[nt][3] = fexp2(s[nt][3] - mn1);
            rs0 += s[nt][0] + s[nt][1];
            rs1 += s[nt][2] + s[nt][3];
        }
        rs0 += __shfl_xor_sync(0xffffffffu, rs0, 1);
        rs0 += __shfl_xor_sync(0xffffffffu, rs0, 2);
        rs1 += __shfl_xor_sync(0xffffffffu, rs1, 1);
        rs1 += __shfl_xor_sync(0xffffffffu, rs1, 2);

        l0 = l0 * al0 + rs0;
        l1 = l1 * al1 + rs1;
#pragma unroll
        for (int nt = 0; nt < 8; ++nt) {
            oa[nt][0] *= al0; oa[nt][1] *= al0;
            oa[nt][2] *= al1; oa[nt][3] *= al1;
        }

        // Write P (tf32 bits) into QP — warp-private rows
        {
            const int pr0 = 16 * warp + grp;
#pragma unroll
            for (int nt = 0; nt < 8; ++nt) {
                int cb = nt * 8 + 2 * tig;
                float2 w0 = { __uint_as_float(tf32cvt(s[nt][0])),
                              __uint_as_float(tf32cvt(s[nt][1])) };
                float2 w1 = { __uint_as_float(tf32cvt(s[nt][2])),
                              __uint_as_float(tf32cvt(s[nt][3])) };
                *(float2*)&QP[pr0 * SQP + cb]       = w0;
                *(float2*)&QP[(pr0 + 8) * SQP + cb] = w1;
            }
        }
        __syncwarp();

        // O += P @ V
#pragma unroll
        for (int ks = 0; ks < 8; ++ks) {
            const int pb = (16 * warp + grp) * SQP + ks * 8 + tig;
            unsigned pa[4];
            pa[0] = __float_as_uint(QP[pb]);
            pa[1] = __float_as_uint(QP[pb + 8 * SQP]);
            pa[2] = __float_as_uint(QP[pb + 4]);
            pa[3] = __float_as_uint(QP[pb + 8 * SQP + 4]);
#pragma unroll
            for (int nt = 0; nt < 8; ++nt) {
                int vaddr = (ks * 8 + tig) * SVV + nt * 8 + grp;
                unsigned bfr[2];
                bfr[0] = __float_as_uint(Vs[vaddr]);
                bfr[1] = __float_as_uint(Vs[vaddr + 4 * SVV]);
                mma_tf32(oa[nt], pa, bfr);
            }
        }
    }

    // Epilogue: normalize, write y as [B,T,H,D] == [B,T,C]
    const float i0 = 1.f / l0, i1 = 1.f / l1;
    const int t0 = rwarp0 + grp;
#pragma unroll
    for (int nt = 0; nt < 8; ++nt) {
        int d = nt * 8 + 2 * tig;
        float2 w0 = { oa[nt][0] * i0, oa[nt][1] * i0 };
        float2 w1 = { oa[nt][2] * i1, oa[nt][3] * i1 };
        *(float2*)(Y + ((size_t)(b * T_ + t0)     * H_ + h) * D_ + d) = w0;
        *(float2*)(Y + ((size_t)(b * T_ + t0 + 8) * H_ + h) * D_ + d) = w1;
    }
}

// ---------------------------------------------------------------------------
extern "C" void kernel_launch(void* const* d_in, const int* in_sizes, int n_in,
                              void* d_out, int out_size)
{
    const float* x      = (const float*)d_in[0];   // [B,T,C]
    const float* W_attn = (const float*)d_in[1];   // [C,3C]
    const float* W_proj = (const float*)d_in[2];   // [C,C]
    float* out = (float*)d_out;                    // [B,T,C]

    float *qkv, *q, *k, *v, *y;
    cudaGetSymbolAddress((void**)&qkv, g_qkv);
    cudaGetSymbolAddress((void**)&q,   g_q);
    cudaGetSymbolAddress((void**)&k,   g_k);
    cudaGetSymbolAddress((void**)&v,   g_v);
    cudaGetSymbolAddress((void**)&y,   g_y);

    cudaFuncSetAttribute(attn_k, cudaFuncAttributeMaxDynamicSharedMemorySize, ATT_SMEM);

    // 1) QKV GEMM (tf32 tensor cores): [8192,1024] @ [1024,3072]
    {
        dim3 grid(F3_ / 128, BT_ / 128);
        tf32gemm_k<<<grid, 256>>>(x, W_attn, qkv, BT_, F3_, C_);
    }
    // 2) RoPE + split/transpose
    {
        int total = B_ * T_ * H_ * (D_ / 2);
        rope_split_k<<<total / 256, 256>>>(qkv, q, k, v);
    }
    // 3) Tensor-core causal flash attention (q-tile 128)
    {
        dim3 grid(T_ / 128, H_, B_);
        attn_k<<<grid, 256, ATT_SMEM>>>(q, k, v, y);
    }
    // 4) Projection GEMM (tf32 tensor cores): [8192,1024] @ [1024,1024]
    {
        dim3 grid(C_ / 128, BT_ / 128);
        tf32gemm_k<<<grid, 256>>>(y, W_proj, out, BT_, C_, C_);
    }
}

// round 10
// speedup vs baseline: 2.8352x; 1.1830x over previous
#include <cuda_runtime.h>
#include <math.h>
#include <float.h>

// Problem constants
#define B_   4
#define T_   2048
#define C_   1024
#define H_   16
#define D_   64
#define BT_  (B_*T_)           // 8192
#define F3_  (3*C_)            // 3072

// Scratch (static device globals: alloc-free, graph-safe)
__device__ float g_qkv[(size_t)BT_ * F3_];        // [B*T, 3C]
__device__ float g_q[(size_t)B_*H_*T_*D_];        // [B,H,T,D]
__device__ float g_k[(size_t)B_*H_*T_*D_];
__device__ float g_v[(size_t)B_*H_*T_*D_];
__device__ float g_y[(size_t)BT_ * C_];           // [B,T,C] (tf32-rounded)
__device__ float g_xc[(size_t)BT_ * C_];          // x,  tf32-rounded
__device__ float g_wac[(size_t)C_ * F3_];         // W_attn, tf32-rounded
__device__ float g_wpc[(size_t)C_ * C_];          // W_proj, tf32-rounded

// FFMA-only exp2 (deg-5, rel err ~2e-6)
__device__ __forceinline__ float fexp2(float x) {
    x = fmaxf(x, -126.f);
    float fl = rintf(x);
    float fr = x - fl;                  // in [-0.5, 0.5]
    float p = 0.0013333558f;
    p = fmaf(p, fr, 0.0096181291f);
    p = fmaf(p, fr, 0.0555041087f);
    p = fmaf(p, fr, 0.2402265069f);
    p = fmaf(p, fr, 0.6931471806f);
    p = fmaf(p, fr, 1.0f);
    return __int_as_float(__float_as_int(p) + (((int)fl) << 23));
}

__device__ __forceinline__ unsigned tf32cvt(float x) {
    unsigned r;
    asm("cvt.rna.tf32.f32 %0, %1;" : "=r"(r) : "f"(x));
    return r;
}

// D += A(16x8,row,tf32) * B(8x8,col,tf32)
__device__ __forceinline__ void mma_tf32(float* d, const unsigned* a, const unsigned* b) {
    asm volatile(
        "mma.sync.aligned.m16n8k8.row.col.f32.tf32.tf32.f32 "
        "{%0,%1,%2,%3}, {%4,%5,%6,%7}, {%8,%9}, {%0,%1,%2,%3};"
        : "+f"(d[0]), "+f"(d[1]), "+f"(d[2]), "+f"(d[3])
        : "r"(a[0]), "r"(a[1]), "r"(a[2]), "r"(a[3]), "r"(b[0]), "r"(b[1]));
}

__device__ __forceinline__ void cpa16(unsigned smem, const float* g) {
    asm volatile("cp.async.cg.shared.global [%0], [%1], 16;" :: "r"(smem), "l"(g));
}

// ---------------------------------------------------------------------------
// Elementwise tf32 rounding pass (inputs pre-converted so the GEMM can
// cp.async raw bits with no in-loop cvt/STS).
// ---------------------------------------------------------------------------
__global__ void cvt_tf32_k(const float* __restrict__ in, float* __restrict__ out, int n4)
{
    int i = blockIdx.x * blockDim.x + threadIdx.x;
    if (i < n4) {
        float4 v = ((const float4*)in)[i];
        float4 w;
        w.x = __uint_as_float(tf32cvt(v.x));
        w.y = __uint_as_float(tf32cvt(v.y));
        w.z = __uint_as_float(tf32cvt(v.z));
        w.w = __uint_as_float(tf32cvt(v.w));
        ((float4*)out)[i] = w;
    }
}

// ---------------------------------------------------------------------------
// tf32 tensor-core GEMM, cp.async 4-stage pipeline.
// C[M,N] = A[M,K] @ B[K,N]; A,B already tf32-rounded in gmem.
// 128x128 tile, BK=16, 256 thr / 8 warps as 2x4 (warp tile 64x32).
// Smem strides: A=20, B=136 (conflict-free fragment loads, cp.async 16B-aligned).
// One barrier per K-tile; wait_group(GS-2) drains the compute stage.
// ---------------------------------------------------------------------------
#define GS 4
#define ASTR 20
#define BSTR 136
#define STAGEF (128*ASTR + 16*BSTR)        // 4736 floats per stage
#define GEMM_SMEM (GS * STAGEF * 4)        // 75776 bytes

__global__ __launch_bounds__(256, 2) void tf32gemm_k(
    const float* __restrict__ A, const float* __restrict__ B,
    float* __restrict__ C, int M, int N, int K)
{
    extern __shared__ float gsm[];
    const unsigned smbase = (unsigned)__cvta_generic_to_shared(gsm);

    const int tid = threadIdx.x;
    const int bm = blockIdx.y * 128;
    const int bn = blockIdx.x * 128;

    const int warp = tid >> 5;
    const int lane = tid & 31;
    const int grp  = lane >> 2;          // 0..7
    const int tig  = lane & 3;           // 0..3
    const int m0   = (warp >> 2) * 64;   // 0 / 64
    const int n0   = (warp & 3) * 32;    // 0..96

    // chunk decompositions (2 x 16B per thread for each of A and B)
    const int ar0 = tid >> 2,  ac0 = (tid & 3) * 4;          // A chunk 0
    const int ar1 = (tid + 256) >> 2, ac1 = ac0;             // A chunk 1 (same col phase)
    const int br0 = tid >> 5,  bc0 = (tid & 31) * 4;         // B chunk 0
    const int br1 = (tid + 256) >> 5, bc1 = bc0;             // B chunk 1

    const float* Abase = A + (size_t)bm * K;
    const float* Bbase = B + bn;

    float acc[4][4][4];
#pragma unroll
    for (int mt = 0; mt < 4; ++mt)
#pragma unroll
        for (int nt = 0; nt < 4; ++nt)
#pragma unroll
            for (int j = 0; j < 4; ++j) acc[mt][nt][j] = 0.f;

    const int ntiles = K >> 4;

#define ISSUE_TILE(stage, t) do {                                              \
        const float* Ag = Abase + (t) * 16;                                    \
        const float* Bg = Bbase + (size_t)((t) * 16) * N;                      \
        unsigned sb = smbase + (stage) * (STAGEF * 4);                         \
        cpa16(sb + (ar0*ASTR + ac0)*4, Ag + (size_t)ar0 * K + ac0);            \
        cpa16(sb + (ar1*ASTR + ac1)*4, Ag + (size_t)ar1 * K + ac1);            \
        cpa16(sb + (128*ASTR + br0*BSTR + bc0)*4, Bg + (size_t)br0 * N + bc0); \
        cpa16(sb + (128*ASTR + br1*BSTR + bc1)*4, Bg + (size_t)br1 * N + bc1); \
    } while (0)

    // Prologue: stages 0..GS-2
#pragma unroll
    for (int s = 0; s < GS - 1; ++s) {
        ISSUE_TILE(s, s);
        asm volatile("cp.async.commit_group;" ::: "memory");
    }

    for (int t = 0; t < ntiles; ++t) {
        asm volatile("cp.async.wait_group %0;" :: "n"(GS - 2) : "memory");
        __syncthreads();   // stage t visible to all; all done computing t-1

        const int tnx = t + GS - 1;
        if (tnx < ntiles) ISSUE_TILE(tnx % GS, tnx);
        asm volatile("cp.async.commit_group;" ::: "memory");

        const float* As_ = gsm + (t % GS) * STAGEF;
        const float* Bs_ = As_ + 128 * ASTR;

#pragma unroll
        for (int kk = 0; kk < 2; ++kk) {
            unsigned bf[4][2];
#pragma unroll
            for (int nt = 0; nt < 4; ++nt) {
                bf[nt][0] = __float_as_uint(Bs_[(kk*8 + tig    ) * BSTR + n0 + nt*8 + grp]);
                bf[nt][1] = __float_as_uint(Bs_[(kk*8 + tig + 4) * BSTR + n0 + nt*8 + grp]);
            }
#pragma unroll
            for (int mt = 0; mt < 4; ++mt) {
                const int r = m0 + mt*16 + grp;
                unsigned af[4];
                af[0] = __float_as_uint(As_[r       * ASTR + kk*8 + tig]);
                af[1] = __float_as_uint(As_[(r + 8) * ASTR + kk*8 + tig]);
                af[2] = __float_as_uint(As_[r       * ASTR + kk*8 + tig + 4]);
                af[3] = __float_as_uint(As_[(r + 8) * ASTR + kk*8 + tig + 4]);
#pragma unroll
                for (int nt = 0; nt < 4; ++nt)
                    mma_tf32(acc[mt][nt], af, bf[nt]);
            }
        }
    }
#undef ISSUE_TILE

    // Epilogue
#pragma unroll
    for (int mt = 0; mt < 4; ++mt) {
        const int row = bm + m0 + mt*16 + grp;
#pragma unroll
        for (int nt = 0; nt < 4; ++nt) {
            const int col = bn + n0 + nt*8 + 2*tig;
            float2 w0 = { acc[mt][nt][0], acc[mt][nt][1] };
            float2 w1 = { acc[mt][nt][2], acc[mt][nt][3] };
            *(float2*)&C[(size_t)row * N + col]       = w0;
            *(float2*)&C[(size_t)(row + 8) * N + col] = w1;
        }
    }
}

// ---------------------------------------------------------------------------
// RoPE + split + transpose: qkv[B,T,3C] -> q,k (roped) and v in [B,H,T,D]
// ---------------------------------------------------------------------------
__global__ void rope_split_k(const float* __restrict__ qkv,
                             float* __restrict__ q,
                             float* __restrict__ k,
                             float* __restrict__ v)
{
    const int idx = blockIdx.x * blockDim.x + threadIdx.x;
    const int p = idx & 31;
    const int h = (idx >> 5) & 15;
    const int t = (idx >> 9) & 2047;
    const int b = idx >> 20;

    const float* base = qkv + (size_t)(b * T_ + t) * F3_;
    const int c = h * D_ + 2 * p;

    const float q1 = base[c],          q2 = base[c + 1];
    const float k1 = base[C_ + c],     k2 = base[C_ + c + 1];
    const float v1 = base[2*C_ + c],   v2 = base[2*C_ + c + 1];

    const float inv = exp2f(-(float)(2 * p) * (13.287712379549449f / 64.f));
    const float ang = (float)t * inv;
    float sn, cs;
    sincosf(ang, &sn, &cs);

    const size_t o = ((size_t)((b * H_ + h) * T_ + t)) * D_ + 2 * p;
    q[o]     = q1 * cs - q2 * sn;
    q[o + 1] = q1 * sn + q2 * cs;
    k[o]     = k1 * cs - k2 * sn;
    k[o + 1] = k1 * sn + k2 * cs;
    v[o]     = v1;
    v[o + 1] = v2;
}

// ---------------------------------------------------------------------------
// Tensor-core causal flash attention (tf32 mma.sync.m16n8k8). Same as the
// passing R9 kernel; epilogue now stores y tf32-rounded (feeds proj GEMM).
// ---------------------------------------------------------------------------
#define SQP 76
#define SKK 76
#define SVV 72
#define ATT_SMEM ((128*SQP + 64*SKK + 64*SVV) * 4)   // 76800 bytes

__global__ __launch_bounds__(256) void attn_k(
    const float* __restrict__ Q, const float* __restrict__ K,
    const float* __restrict__ V, float* __restrict__ Y)
{
    extern __shared__ float sm[];
    float* QP = sm;                 // [128][SQP]  Q staging, then P
    float* Ks = sm + 128*SQP;       // [64][SKK]   tf32 bits
    float* Vs = Ks + 64*SKK;        // [64][SVV]   tf32 bits

    const int qb = (int)gridDim.x - 1 - (int)blockIdx.x;  // largest first
    const int h  = blockIdx.y;
    const int b  = blockIdx.z;
    const int bh = b * H_ + h;
    const int q0 = qb * 128;

    const float* Qg = Q + (size_t)bh * T_ * D_;
    const float* Kg = K + (size_t)bh * T_ * D_;
    const float* Vg = V + (size_t)bh * T_ * D_;

    const int tid  = threadIdx.x;
    const int warp = tid >> 5;
    const int lane = tid & 31;
    const int grp  = lane >> 2;      // 0..7
    const int tig  = lane & 3;       // 0..3

    // Stage Q tile (128x64) into QP
#pragma unroll
    for (int i = 0; i < 8; ++i) {
        int idx = tid + 256 * i;
        int row = idx >> 4;
        int c4  = (idx & 15) * 4;
        *(float4*)&QP[row * SQP + c4] = *(const float4*)&Qg[(size_t)(q0 + row) * D_ + c4];
    }
    __syncthreads();

    // Hoist Q A-fragments (scale folded: 1/8 * log2(e)), tf32
    const float scale2 = 0.125f * 1.4426950408889634f;
    unsigned qa[8][4];
    {
        const int r0 = 16 * warp + grp;
#pragma unroll
        for (int ks = 0; ks < 8; ++ks) {
            int cbase = ks * 8 + tig;
            qa[ks][0] = tf32cvt(QP[r0 * SQP + cbase] * scale2);
            qa[ks][1] = tf32cvt(QP[(r0 + 8) * SQP + cbase] * scale2);
            qa[ks][2] = tf32cvt(QP[r0 * SQP + cbase + 4] * scale2);
            qa[ks][3] = tf32cvt(QP[(r0 + 8) * SQP + cbase + 4] * scale2);
        }
    }

    float m0 = -INFINITY, m1 = -INFINITY, l0 = 0.f, l1 = 0.f;
    float oa[8][4];
#pragma unroll
    for (int nt = 0; nt < 8; ++nt)
#pragma unroll
        for (int j = 0; j < 4; ++j) oa[nt][j] = 0.f;

    const int nk = 2 * qb + 2;              // 64-wide k tiles
    const int rwarp0 = q0 + 16 * warp;      // warp's first global row

    for (int kt = 0; kt < nk; ++kt) {
        const int k0 = kt * 64;
        __syncthreads();

        // Load K,V tiles, converting to tf32 at store
#pragma unroll
        for (int i = 0; i < 4; ++i) {
            int idx = tid + 256 * i;
            int row = idx >> 4;
            int c4  = (idx & 15) * 4;
            float4 kv = *(const float4*)&Kg[(size_t)(k0 + row) * D_ + c4];
            float4 vv = *(const float4*)&Vg[(size_t)(k0 + row) * D_ + c4];
            float* kd = &Ks[row * SKK + c4];
            kd[0] = __uint_as_float(tf32cvt(kv.x));
            kd[1] = __uint_as_float(tf32cvt(kv.y));
            kd[2] = __uint_as_float(tf32cvt(kv.z));
            kd[3] = __uint_as_float(tf32cvt(kv.w));
            float* vd = &Vs[row * SVV + c4];
            vd[0] = __uint_as_float(tf32cvt(vv.x));
            vd[1] = __uint_as_float(tf32cvt(vv.y));
            vd[2] = __uint_as_float(tf32cvt(vv.z));
            vd[3] = __uint_as_float(tf32cvt(vv.w));
        }
        __syncthreads();

        // S = (Q*scale) @ K^T
        float s[8][4];
#pragma unroll
        for (int nt = 0; nt < 8; ++nt)
#pragma unroll
            for (int j = 0; j < 4; ++j) s[nt][j] = 0.f;

#pragma unroll
        for (int ks = 0; ks < 8; ++ks) {
#pragma unroll
            for (int nt = 0; nt < 8; ++nt) {
                int naddr = (nt * 8 + grp) * SKK + ks * 8 + tig;
                unsigned bfr[2];
                bfr[0] = __float_as_uint(Ks[naddr]);
                bfr[1] = __float_as_uint(Ks[naddr + 4]);
                mma_tf32(s[nt], qa[ks], bfr);
            }
        }

        // Causal mask (gate on warp's MIN row)
        if (k0 + 63 > rwarp0) {
            const int r0g = rwarp0 + grp;
#pragma unroll
            for (int nt = 0; nt < 8; ++nt) {
                int cb = k0 + nt * 8 + 2 * tig;
                if (cb     > r0g)     s[nt][0] = -INFINITY;
                if (cb + 1 > r0g)     s[nt][1] = -INFINITY;
                if (cb     > r0g + 8) s[nt][2] = -INFINITY;
                if (cb + 1 > r0g + 8) s[nt][3] = -INFINITY;
            }
        }

        // Warp-private online softmax
        float rm0 = -INFINITY, rm1 = -INFINITY;
#pragma unroll
        for (int nt = 0; nt < 8; ++nt) {
            rm0 = fmaxf(rm0, fmaxf(s[nt][0], s[nt][1]));
            rm1 = fmaxf(rm1, fmaxf(s[nt][2], s[nt][3]));
        }
        rm0 = fmaxf(rm0, __shfl_xor_sync(0xffffffffu, rm0, 1));
        rm0 = fmaxf(rm0, __shfl_xor_sync(0xffffffffu, rm0, 2));
        rm1 = fmaxf(rm1, __shfl_xor_sync(0xffffffffu, rm1, 1));
        rm1 = fmaxf(rm1, __shfl_xor_sync(0xffffffffu, rm1, 2));

        float mn0 = fmaxf(m0, rm0), mn1 = fmaxf(m1, rm1);
        float al0 = fexp2(m0 - mn0), al1 = fexp2(m1 - mn1);
        m0 = mn0; m1 = mn1;

        float rs0 = 0.f, rs1 = 0.f;
#pragma unroll
        for (int nt = 0; nt < 8; ++nt) {
            s[nt][0] = fexp2(s[nt][0] - mn0);
            s[nt][1] = fexp2(s[nt][1] - mn0);
            s[nt][2] = fexp2(s[nt][2] - mn1);
            s[nt][3] = fexp2(s[nt][3] - mn1);
            rs0 += s[nt][0] + s[nt][1];
            rs1 += s[nt][2] + s[nt][3];
        }
        rs0 += __shfl_xor_sync(0xffffffffu, rs0, 1);
        rs0 += __shfl_xor_sync(0xffffffffu, rs0, 2);
        rs1 += __shfl_xor_sync(0xffffffffu, rs1, 1);
        rs1 += __shfl_xor_sync(0xffffffffu, rs1, 2);

        l0 = l0 * al0 + rs0;
        l1 = l1 * al1 + rs1;
#pragma unroll
        for (int nt = 0; nt < 8; ++nt) {
            oa[nt][0] *= al0; oa[nt][1] *= al0;
            oa[nt][2] *= al1; oa[nt][3] *= al1;
        }

        // Write P (tf32 bits) into QP — warp-private rows
        {
            const int pr0 = 16 * warp + grp;
#pragma unroll
            for (int nt = 0; nt < 8; ++nt) {
                int cb = nt * 8 + 2 * tig;
                float2 w0 = { __uint_as_float(tf32cvt(s[nt][0])),
                              __uint_as_float(tf32cvt(s[nt][1])) };
                float2 w1 = { __uint_as_float(tf32cvt(s[nt][2])),
                              __uint_as_float(tf32cvt(s[nt][3])) };
                *(float2*)&QP[pr0 * SQP + cb]       = w0;
                *(float2*)&QP[(pr0 + 8) * SQP + cb] = w1;
            }
        }
        __syncwarp();

        // O += P @ V
#pragma unroll
        for (int ks = 0; ks < 8; ++ks) {
            const int pb = (16 * warp + grp) * SQP + ks * 8 + tig;
            unsigned pa[4];
            pa[0] = __float_as_uint(QP[pb]);
            pa[1] = __float_as_uint(QP[pb + 8 * SQP]);
            pa[2] = __float_as_uint(QP[pb + 4]);
            pa[3] = __float_as_uint(QP[pb + 8 * SQP + 4]);
#pragma unroll
            for (int nt = 0; nt < 8; ++nt) {
                int vaddr = (ks * 8 + tig) * SVV + nt * 8 + grp;
                unsigned bfr[2];
                bfr[0] = __float_as_uint(Vs[vaddr]);
                bfr[1] = __float_as_uint(Vs[vaddr + 4 * SVV]);
                mma_tf32(oa[nt], pa, bfr);
            }
        }
    }

    // Epilogue: normalize, tf32-round (proj GEMM input), write [B,T,H,D]
    const float i0 = 1.f / l0, i1 = 1.f / l1;
    const int t0 = rwarp0 + grp;
#pragma unroll
    for (int nt = 0; nt < 8; ++nt) {
        int d = nt * 8 + 2 * tig;
        float2 w0 = { __uint_as_float(tf32cvt(oa[nt][0] * i0)),
                      __uint_as_float(tf32cvt(oa[nt][1] * i0)) };
        float2 w1 = { __uint_as_float(tf32cvt(oa[nt][2] * i1)),
                      __uint_as_float(tf32cvt(oa[nt][3] * i1)) };
        *(float2*)(Y + ((size_t)(b * T_ + t0)     * H_ + h) * D_ + d) = w0;
        *(float2*)(Y + ((size_t)(b * T_ + t0 + 8) * H_ + h) * D_ + d) = w1;
    }
}

// ---------------------------------------------------------------------------
extern "C" void kernel_launch(void* const* d_in, const int* in_sizes, int n_in,
                              void* d_out, int out_size)
{
    const float* x      = (const float*)d_in[0];   // [B,T,C]
    const float* W_attn = (const float*)d_in[1];   // [C,3C]
    const float* W_proj = (const float*)d_in[2];   // [C,C]
    float* out = (float*)d_out;                    // [B,T,C]

    float *qkv, *q, *k, *v, *y, *xc, *wac, *wpc;
    cudaGetSymbolAddress((void**)&qkv, g_qkv);
    cudaGetSymbolAddress((void**)&q,   g_q);
    cudaGetSymbolAddress((void**)&k,   g_k);
    cudaGetSymbolAddress((void**)&v,   g_v);
    cudaGetSymbolAddress((void**)&y,   g_y);
    cudaGetSymbolAddress((void**)&xc,  g_xc);
    cudaGetSymbolAddress((void**)&wac, g_wac);
    cudaGetSymbolAddress((void**)&wpc, g_wpc);

    cudaFuncSetAttribute(attn_k, cudaFuncAttributeMaxDynamicSharedMemorySize, ATT_SMEM);
    cudaFuncSetAttribute(tf32gemm_k, cudaFuncAttributeMaxDynamicSharedMemorySize, GEMM_SMEM);

    // 0) Pre-round GEMM inputs to tf32 (lets GEMM cp.async raw bits)
    cvt_tf32_k<<<(BT_*C_/4 + 255)/256, 256>>>(x, xc, BT_*C_/4);
    cvt_tf32_k<<<(C_*F3_/4 + 255)/256, 256>>>(W_attn, wac, C_*F3_/4);
    cvt_tf32_k<<<(C_*C_/4 + 255)/256, 256>>>(W_proj, wpc, C_*C_/4);

    // 1) QKV GEMM (tf32, cp.async): [8192,1024] @ [1024,3072]
    {
        dim3 grid(F3_ / 128, BT_ / 128);
        tf32gemm_k<<<grid, 256, GEMM_SMEM>>>(xc, wac, qkv, BT_, F3_, C_);
    }
    // 2) RoPE + split/transpose
    {
        int total = B_ * T_ * H_ * (D_ / 2);
        rope_split_k<<<total / 256, 256>>>(qkv, q, k, v);
    }
    // 3) Tensor-core causal flash attention (q-tile 128)
    {
        dim3 grid(T_ / 128, H_, B_);
        attn_k<<<grid, 256, ATT_SMEM>>>(q, k, v, y);
    }
    // 4) Projection GEMM (tf32, cp.async): [8192,1024] @ [1024,1024]
    {
        dim3 grid(C_ / 128, BT_ / 128);
        tf32gemm_k<<<grid, 256, GEMM_SMEM>>>(y, wpc, out, BT_, C_, C_);
    }
}

// round 12
// speedup vs baseline: 2.9601x; 1.0441x over previous
#include <cuda_runtime.h>
#include <math.h>
#include <float.h>

// Problem constants
#define B_   4
#define T_   2048
#define C_   1024
#define H_   16
#define D_   64
#define BT_  (B_*T_)           // 8192
#define F3_  (3*C_)            // 3072

// Scratch (static device globals: alloc-free, graph-safe)
__device__ float g_qkv[(size_t)BT_ * F3_];        // [B*T, 3C]
__device__ float g_q[(size_t)B_*H_*T_*D_];        // [B,H,T,D] tf32-rounded
__device__ float g_k[(size_t)B_*H_*T_*D_];        // tf32-rounded
__device__ float g_v[(size_t)B_*H_*T_*D_];        // tf32-rounded
__device__ float g_y[(size_t)BT_ * C_];           // [B,T,C] tf32-rounded
__device__ float g_xc[(size_t)BT_ * C_];          // x,  tf32-rounded
__device__ float g_wac[(size_t)C_ * F3_];         // W_attn, tf32-rounded
__device__ float g_wpc[(size_t)C_ * C_];          // W_proj, tf32-rounded

// FFMA-only exp2 (deg-5, rel err ~2e-6)
__device__ __forceinline__ float fexp2(float x) {
    x = fmaxf(x, -126.f);
    float fl = rintf(x);
    float fr = x - fl;                  // in [-0.5, 0.5]
    float p = 0.0013333558f;
    p = fmaf(p, fr, 0.0096181291f);
    p = fmaf(p, fr, 0.0555041087f);
    p = fmaf(p, fr, 0.2402265069f);
    p = fmaf(p, fr, 0.6931471806f);
    p = fmaf(p, fr, 1.0f);
    return __int_as_float(__float_as_int(p) + (((int)fl) << 23));
}

__device__ __forceinline__ unsigned tf32cvt(float x) {
    unsigned r;
    asm("cvt.rna.tf32.f32 %0, %1;" : "=r"(r) : "f"(x));
    return r;
}

// D += A(16x8,row,tf32) * B(8x8,col,tf32)
__device__ __forceinline__ void mma_tf32(float* d, const unsigned* a, const unsigned* b) {
    asm volatile(
        "mma.sync.aligned.m16n8k8.row.col.f32.tf32.tf32.f32 "
        "{%0,%1,%2,%3}, {%4,%5,%6,%7}, {%8,%9}, {%0,%1,%2,%3};"
        : "+f"(d[0]), "+f"(d[1]), "+f"(d[2]), "+f"(d[3])
        : "r"(a[0]), "r"(a[1]), "r"(a[2]), "r"(a[3]), "r"(b[0]), "r"(b[1]));
}

__device__ __forceinline__ void cpa16(unsigned smem, const float* g) {
    asm volatile("cp.async.cg.shared.global [%0], [%1], 16;" :: "r"(smem), "l"(g));
}

// ---------------------------------------------------------------------------
// Elementwise tf32 rounding pass
// ---------------------------------------------------------------------------
__global__ void cvt_tf32_k(const float* __restrict__ in, float* __restrict__ out, int n4)
{
    int i = blockIdx.x * blockDim.x + threadIdx.x;
    if (i < n4) {
        float4 v = ((const float4*)in)[i];
        float4 w;
        w.x = __uint_as_float(tf32cvt(v.x));
        w.y = __uint_as_float(tf32cvt(v.y));
        w.z = __uint_as_float(tf32cvt(v.z));
        w.w = __uint_as_float(tf32cvt(v.w));
        ((float4*)out)[i] = w;
    }
}

// ---------------------------------------------------------------------------
// tf32 tensor-core GEMM, cp.async 3-stage pipeline, BK=32.
// C[M,N] = A[M,K] @ B[K,N]; A,B already tf32-rounded in gmem.
// 128x128 tile, 256 thr / 8 warps as 2x4 (warp tile 64x32).
// One barrier per 64 mma. ASTR=36, BSTR=136 (conflict-free fragment loads).
// ---------------------------------------------------------------------------
#define GS 3
#define BK 32
#define ASTR 36
#define BSTR 136
#define STAGEF (128*ASTR + BK*BSTR)        // 8960 floats per stage
#define GEMM_SMEM (GS * STAGEF * 4)        // 107520 bytes

__global__ __launch_bounds__(256, 2) void tf32gemm_k(
    const float* __restrict__ A, const float* __restrict__ B,
    float* __restrict__ C, int M, int N, int K)
{
    extern __shared__ float gsm[];
    const unsigned smbase = (unsigned)__cvta_generic_to_shared(gsm);

    const int tid = threadIdx.x;
    const int bm = blockIdx.y * 128;
    const int bn = blockIdx.x * 128;

    const int warp = tid >> 5;
    const int lane = tid & 31;
    const int grp  = lane >> 2;          // 0..7
    const int tig  = lane & 3;           // 0..3
    const int m0   = (warp >> 2) * 64;   // 0 / 64
    const int n0   = (warp & 3) * 32;    // 0..96

    const float* Abase = A + (size_t)bm * K;
    const float* Bbase = B + bn;

    float acc[4][4][4];
#pragma unroll
    for (int mt = 0; mt < 4; ++mt)
#pragma unroll
        for (int nt = 0; nt < 4; ++nt)
#pragma unroll
            for (int j = 0; j < 4; ++j) acc[mt][nt][j] = 0.f;

    const int ntiles = K >> 5;

    // A: 128x32 (8 chunks/row), B: 32x128 (32 chunks/row); 4 chunks each.
#define ISSUE_TILE(stage, t) do {                                              \
        const float* Ag = Abase + (t) * BK;                                    \
        const float* Bg = Bbase + (size_t)((t) * BK) * N;                      \
        unsigned sb = smbase + (stage) * (STAGEF * 4);                         \
        _Pragma("unroll")                                                      \
        for (int ci = 0; ci < 4; ++ci) {                                       \
            int ai = tid + 256 * ci;                                           \
            int ar = ai >> 3, ac = (ai & 7) * 4;                               \
            cpa16(sb + (ar*ASTR + ac)*4, Ag + (size_t)ar * K + ac);            \
            int bi = tid + 256 * ci;                                           \
            int br = bi >> 5, bc = (bi & 31) * 4;                              \
            cpa16(sb + (128*ASTR + br*BSTR + bc)*4, Bg + (size_t)br * N + bc); \
        }                                                                      \
    } while (0)

    // Prologue: stages 0..GS-2
#pragma unroll
    for (int s = 0; s < GS - 1; ++s) {
        ISSUE_TILE(s, s);
        asm volatile("cp.async.commit_group;" ::: "memory");
    }

    for (int t = 0; t < ntiles; ++t) {
        asm volatile("cp.async.wait_group %0;" :: "n"(GS - 2) : "memory");
        __syncthreads();   // stage t visible; all warps done with t-1's stage

        const int tnx = t + GS - 1;
        if (tnx < ntiles) ISSUE_TILE(tnx % GS, tnx);
        asm volatile("cp.async.commit_group;" ::: "memory");

        const float* As_ = gsm + (t % GS) * STAGEF;
        const float* Bs_ = As_ + 128 * ASTR;

#pragma unroll
        for (int kk = 0; kk < 4; ++kk) {
            unsigned bf[4][2];
#pragma unroll
            for (int nt = 0; nt < 4; ++nt) {
                bf[nt][0] = __float_as_uint(Bs_[(kk*8 + tig    ) * BSTR + n0 + nt*8 + grp]);
                bf[nt][1] = __float_as_uint(Bs_[(kk*8 + tig + 4) * BSTR + n0 + nt*8 + grp]);
            }
#pragma unroll
            for (int mt = 0; mt < 4; ++mt) {
                const int r = m0 + mt*16 + grp;
                unsigned af[4];
                af[0] = __float_as_uint(As_[r       * ASTR + kk*8 + tig]);
                af[1] = __float_as_uint(As_[(r + 8) * ASTR + kk*8 + tig]);
                af[2] = __float_as_uint(As_[r       * ASTR + kk*8 + tig + 4]);
                af[3] = __float_as_uint(As_[(r + 8) * ASTR + kk*8 + tig + 4]);
#pragma unroll
                for (int nt = 0; nt < 4; ++nt)
                    mma_tf32(acc[mt][nt], af, bf[nt]);
            }
        }
    }
#undef ISSUE_TILE

    // Epilogue
#pragma unroll
    for (int mt = 0; mt < 4; ++mt) {
        const int row = bm + m0 + mt*16 + grp;
#pragma unroll
        for (int nt = 0; nt < 4; ++nt) {
            const int col = bn + n0 + nt*8 + 2*tig;
            float2 w0 = { acc[mt][nt][0], acc[mt][nt][1] };
            float2 w1 = { acc[mt][nt][2], acc[mt][nt][3] };
            *(float2*)&C[(size_t)row * N + col]       = w0;
            *(float2*)&C[(size_t)(row + 8) * N + col] = w1;
        }
    }
}

// ---------------------------------------------------------------------------
// RoPE + split + transpose; outputs tf32-ROUNDED q,k,v so attention can
// stage K/V with raw float4 copies (no in-loop cvt).
// ---------------------------------------------------------------------------
__global__ void rope_split_k(const float* __restrict__ qkv,
                             float* __restrict__ q,
                             float* __restrict__ k,
                             float* __restrict__ v)
{
    const int idx = blockIdx.x * blockDim.x + threadIdx.x;
    const int p = idx & 31;
    const int h = (idx >> 5) & 15;
    const int t = (idx >> 9) & 2047;
    const int b = idx >> 20;

    const float* base = qkv + (size_t)(b * T_ + t) * F3_;
    const int c = h * D_ + 2 * p;

    const float q1 = base[c],          q2 = base[c + 1];
    const float k1 = base[C_ + c],     k2 = base[C_ + c + 1];
    const float v1 = base[2*C_ + c],   v2 = base[2*C_ + c + 1];

    const float inv = exp2f(-(float)(2 * p) * (13.287712379549449f / 64.f));
    const float ang = (float)t * inv;
    float sn, cs;
    sincosf(ang, &sn, &cs);

    const size_t o = ((size_t)((b * H_ + h) * T_ + t)) * D_ + 2 * p;
    q[o]     = __uint_as_float(tf32cvt(q1 * cs - q2 * sn));
    q[o + 1] = __uint_as_float(tf32cvt(q1 * sn + q2 * cs));
    k[o]     = __uint_as_float(tf32cvt(k1 * cs - k2 * sn));
    k[o + 1] = __uint_as_float(tf32cvt(k1 * sn + k2 * cs));
    v[o]     = __uint_as_float(tf32cvt(v1));
    v[o + 1] = __uint_as_float(tf32cvt(v2));
}

// ---------------------------------------------------------------------------
// Tensor-core causal flash attention (tf32 mma.sync.m16n8k8).
// K/V arrive pre-rounded -> staging is pure LDG.128/STS.128.
// ---------------------------------------------------------------------------
#define SQP 76
#define SKK 76
#define SVV 72
#define ATT_SMEM ((128*SQP + 64*SKK + 64*SVV) * 4)   // 76800 bytes

__global__ __launch_bounds__(256) void attn_k(
    const float* __restrict__ Q, const float* __restrict__ K,
    const float* __restrict__ V, float* __restrict__ Y)
{
    extern __shared__ float sm[];
    float* QP = sm;                 // [128][SQP]  Q staging, then P
    float* Ks = sm + 128*SQP;       // [64][SKK]
    float* Vs = Ks + 64*SKK;        // [64][SVV]

    const int qb = (int)gridDim.x - 1 - (int)blockIdx.x;  // largest first
    const int h  = blockIdx.y;
    const int b  = blockIdx.z;
    const int bh = b * H_ + h;
    const int q0 = qb * 128;

    const float* Qg = Q + (size_t)bh * T_ * D_;
    const float* Kg = K + (size_t)bh * T_ * D_;
    const float* Vg = V + (size_t)bh * T_ * D_;

    const int tid  = threadIdx.x;
    const int warp = tid >> 5;
    const int lane = tid & 31;
    const int grp  = lane >> 2;      // 0..7
    const int tig  = lane & 3;       // 0..3

    // Stage Q tile (128x64) into QP
#pragma unroll
    for (int i = 0; i < 8; ++i) {
        int idx = tid + 256 * i;
        int row = idx >> 4;
        int c4  = (idx & 15) * 4;
        *(float4*)&QP[row * SQP + c4] = *(const float4*)&Qg[(size_t)(q0 + row) * D_ + c4];
    }
    __syncthreads();

    // Hoist Q A-fragments (scale folded: 1/8 * log2(e)), re-round to tf32
    const float scale2 = 0.125f * 1.4426950408889634f;
    unsigned qa[8][4];
    {
        const int r0 = 16 * warp + grp;
#pragma unroll
        for (int ks = 0; ks < 8; ++ks) {
            int cbase = ks * 8 + tig;
            qa[ks][0] = tf32cvt(QP[r0 * SQP + cbase] * scale2);
            qa[ks][1] = tf32cvt(QP[(r0 + 8) * SQP + cbase] * scale2);
            qa[ks][2] = tf32cvt(QP[r0 * SQP + cbase + 4] * scale2);
            qa[ks][3] = tf32cvt(QP[(r0 + 8) * SQP + cbase + 4] * scale2);
        }
    }

    float m0 = -INFINITY, m1 = -INFINITY, l0 = 0.f, l1 = 0.f;
    float oa[8][4];
#pragma unroll
    for (int nt = 0; nt < 8; ++nt)
#pragma unroll
        for (int j = 0; j < 4; ++j) oa[nt][j] = 0.f;

    const int nk = 2 * qb + 2;              // 64-wide k tiles
    const int rwarp0 = q0 + 16 * warp;      // warp's first global row

    for (int kt = 0; kt < nk; ++kt) {
        const int k0 = kt * 64;
        __syncthreads();

        // Load K,V tiles (already tf32 bits): raw float4 copies
#pragma unroll
        for (int i = 0; i < 4; ++i) {
            int idx = tid + 256 * i;
            int row = idx >> 4;
            int c4  = (idx & 15) * 4;
            *(float4*)&Ks[row * SKK + c4] = *(const float4*)&Kg[(size_t)(k0 + row) * D_ + c4];
            *(float4*)&Vs[row * SVV + c4] = *(const float4*)&Vg[(size_t)(k0 + row) * D_ + c4];
        }
        __syncthreads();

        // S = (Q*scale) @ K^T
        float s[8][4];
#pragma unroll
        for (int nt = 0; nt < 8; ++nt)
#pragma unroll
            for (int j = 0; j < 4; ++j) s[nt][j] = 0.f;

#pragma unroll
        for (int ks = 0; ks < 8; ++ks) {
#pragma unroll
            for (int nt = 0; nt < 8; ++nt) {
                int naddr = (nt * 8 + grp) * SKK + ks * 8 + tig;
                unsigned bfr[2];
                bfr[0] = __float_as_uint(Ks[naddr]);
                bfr[1] = __float_as_uint(Ks[naddr + 4]);
                mma_tf32(s[nt], qa[ks], bfr);
            }
        }

        // Causal mask (gate on warp's MIN row)
        if (k0 + 63 > rwarp0) {
            const int r0g = rwarp0 + grp;
#pragma unroll
            for (int nt = 0; nt < 8; ++nt) {
                int cb = k0 + nt * 8 + 2 * tig;
                if (cb     > r0g)     s[nt][0] = -INFINITY;
                if (cb + 1 > r0g)     s[nt][1] = -INFINITY;
                if (cb     > r0g + 8) s[nt][2] = -INFINITY;
                if (cb + 1 > r0g + 8) s[nt][3] = -INFINITY;
            }
        }

        // Warp-private online softmax
        float rm0 = -INFINITY, rm1 = -INFINITY;
#pragma unroll
        for (int nt = 0; nt < 8; ++nt) {
            rm0 = fmaxf(rm0, fmaxf(s[nt][0], s[nt][1]));
            rm1 = fmaxf(rm1, fmaxf(s[nt][2], s[nt][3]));
        }
        rm0 = fmaxf(rm0, __shfl_xor_sync(0xffffffffu, rm0, 1));
        rm0 = fmaxf(rm0, __shfl_xor_sync(0xffffffffu, rm0, 2));
        rm1 = fmaxf(rm1, __shfl_xor_sync(0xffffffffu, rm1, 1));
        rm1 = fmaxf(rm1, __shfl_xor_sync(0xffffffffu, rm1, 2));

        float mn0 = fmaxf(m0, rm0), mn1 = fmaxf(m1, rm1);
        float al0 = fexp2(m0 - mn0), al1 = fexp2(m1 - mn1);
        m0 = mn0; m1 = mn1;

        float rs0 = 0.f, rs1 = 0.f;
#pragma unroll
        for (int nt = 0; nt < 8; ++nt) {
            s[nt][0] = fexp2(s[nt][0] - mn0);
            s[nt][1] = fexp2(s[nt][1] - mn0);
            s[nt][2] = fexp2(s[nt][2] - mn1);
            s[nt][3] = fexp2(s[nt][3] - mn1);
            rs0 += s[nt][0] + s[nt][1];
            rs1 += s[nt][2] + s[nt][3];
        }
        rs0 += __shfl_xor_sync(0xffffffffu, rs0, 1);
        rs0 += __shfl_xor_sync(0xffffffffu, rs0, 2);
        rs1 += __shfl_xor_sync(0xffffffffu, rs1, 1);
        rs1 += __shfl_xor_sync(0xffffffffu, rs1, 2);

        l0 = l0 * al0 + rs0;
        l1 = l1 * al1 + rs1;
#pragma unroll
        for (int nt = 0; nt < 8; ++nt) {
            oa[nt][0] *= al0; oa[nt][1] *= al0;
            oa[nt][2] *= al1; oa[nt][3] *= al1;
        }

        // Write P (tf32 bits) into QP — warp-private rows
        {
            const int pr0 = 16 * warp + grp;
#pragma unroll
            for (int nt = 0; nt < 8; ++nt) {
                int cb = nt * 8 + 2 * tig;
                float2 w0 = { __uint_as_float(tf32cvt(s[nt][0])),
                              __uint_as_float(tf32cvt(s[nt][1])) };
                float2 w1 = { __uint_as_float(tf32cvt(s[nt][2])),
                              __uint_as_float(tf32cvt(s[nt][3])) };
                *(float2*)&QP[pr0 * SQP + cb]       = w0;
                *(float2*)&QP[(pr0 + 8) * SQP + cb] = w1;
            }
        }
        __syncwarp();

        // O += P @ V
#pragma unroll
        for (int ks = 0; ks < 8; ++ks) {
            const int pb = (16 * warp + grp) * SQP + ks * 8 + tig;
            unsigned pa[4];
            pa[0] = __float_as_uint(QP[pb]);
            pa[1] = __float_as_uint(QP[pb + 8 * SQP]);
            pa[2] = __float_as_uint(QP[pb + 4]);
            pa[3] = __float_as_uint(QP[pb + 8 * SQP + 4]);
#pragma unroll
            for (int nt = 0; nt < 8; ++nt) {
                int vaddr = (ks * 8 + tig) * SVV + nt * 8 + grp;
                unsigned bfr[2];
                bfr[0] = __float_as_uint(Vs[vaddr]);
                bfr[1] = __float_as_uint(Vs[vaddr + 4 * SVV]);
                mma_tf32(oa[nt], pa, bfr);
            }
        }
    }

    // Epilogue: normalize, tf32-round (proj GEMM input), write [B,T,H,D]
    const float i0 = 1.f / l0, i1 = 1.f / l1;
    const int t0 = rwarp0 + grp;
#pragma unroll
    for (int nt = 0; nt < 8; ++nt) {
        int d = nt * 8 + 2 * tig;
        float2 w0 = { __uint_as_float(tf32cvt(oa[nt][0] * i0)),
                      __uint_as_float(tf32cvt(oa[nt][1] * i0)) };
        float2 w1 = { __uint_as_float(tf32cvt(oa[nt][2] * i1)),
                      __uint_as_float(tf32cvt(oa[nt][3] * i1)) };
        *(float2*)(Y + ((size_t)(b * T_ + t0)     * H_ + h) * D_ + d) = w0;
        *(float2*)(Y + ((size_t)(b * T_ + t0 + 8) * H_ + h) * D_ + d) = w1;
    }
}

// ---------------------------------------------------------------------------
extern "C" void kernel_launch(void* const* d_in, const int* in_sizes, int n_in,
                              void* d_out, int out_size)
{
    const float* x      = (const float*)d_in[0];   // [B,T,C]
    const float* W_attn = (const float*)d_in[1];   // [C,3C]
    const float* W_proj = (const float*)d_in[2];   // [C,C]
    float* out = (float*)d_out;                    // [B,T,C]

    float *qkv, *q, *k, *v, *y, *xc, *wac, *wpc;
    cudaGetSymbolAddress((void**)&qkv, g_qkv);
    cudaGetSymbolAddress((void**)&q,   g_q);
    cudaGetSymbolAddress((void**)&k,   g_k);
    cudaGetSymbolAddress((void**)&v,   g_v);
    cudaGetSymbolAddress((void**)&y,   g_y);
    cudaGetSymbolAddress((void**)&xc,  g_xc);
    cudaGetSymbolAddress((void**)&wac, g_wac);
    cudaGetSymbolAddress((void**)&wpc, g_wpc);

    cudaFuncSetAttribute(attn_k, cudaFuncAttributeMaxDynamicSharedMemorySize, ATT_SMEM);
    cudaFuncSetAttribute(tf32gemm_k, cudaFuncAttributeMaxDynamicSharedMemorySize, GEMM_SMEM);

    // 0) Pre-round GEMM inputs to tf32
    cvt_tf32_k<<<(BT_*C_/4 + 255)/256, 256>>>(x, xc, BT_*C_/4);
    cvt_tf32_k<<<(C_*F3_/4 + 255)/256, 256>>>(W_attn, wac, C_*F3_/4);
    cvt_tf32_k<<<(C_*C_/4 + 255)/256, 256>>>(W_proj, wpc, C_*C_/4);

    // 1) QKV GEMM (tf32, cp.async BK=32): [8192,1024] @ [1024,3072]
    {
        dim3 grid(F3_ / 128, BT_ / 128);
        tf32gemm_k<<<grid, 256, GEMM_SMEM>>>(xc, wac, qkv, BT_, F3_, C_);
    }
    // 2) RoPE + split/transpose (tf32-rounded outputs)
    {
        int total = B_ * T_ * H_ * (D_ / 2);
        rope_split_k<<<total / 256, 256>>>(qkv, q, k, v);
    }
    // 3) Tensor-core causal flash attention (q-tile 128)
    {
        dim3 grid(T_ / 128, H_, B_);
        attn_k<<<grid, 256, ATT_SMEM>>>(q, k, v, y);
    }
    // 4) Projection GEMM (tf32, cp.async BK=32): [8192,1024] @ [1024,1024]
    {
        dim3 grid(C_ / 128, BT_ / 128);
        tf32gemm_k<<<grid, 256, GEMM_SMEM>>>(y, wpc, out, BT_, C_, C_);
    }
}

// round 14
// speedup vs baseline: 3.0147x; 1.0184x over previous
#include <cuda_runtime.h>
#include <math.h>
#include <float.h>

// Problem constants
#define B_   4
#define T_   2048
#define C_   1024
#define H_   16
#define D_   64
#define BT_  (B_*T_)           // 8192
#define F3_  (3*C_)            // 3072

// Scratch (static device globals: alloc-free, graph-safe)
__device__ float g_q[(size_t)B_*H_*T_*D_];        // [B,H,T,D] tf32-rounded
__device__ float g_k[(size_t)B_*H_*T_*D_];        // tf32-rounded
__device__ float g_v[(size_t)B_*H_*T_*D_];        // tf32-rounded
__device__ float g_y[(size_t)BT_ * C_];           // [B,T,C] tf32-rounded
__device__ float g_xc[(size_t)BT_ * C_];          // x,  tf32-rounded
__device__ float g_wac[(size_t)C_ * F3_];         // W_attn, tf32-rounded
__device__ float g_wpc[(size_t)C_ * C_];          // W_proj, tf32-rounded

// FFMA-only exp2 (deg-5, rel err ~2e-6)
__device__ __forceinline__ float fexp2(float x) {
    x = fmaxf(x, -126.f);
    float fl = rintf(x);
    float fr = x - fl;                  // in [-0.5, 0.5]
    float p = 0.0013333558f;
    p = fmaf(p, fr, 0.0096181291f);
    p = fmaf(p, fr, 0.0555041087f);
    p = fmaf(p, fr, 0.2402265069f);
    p = fmaf(p, fr, 0.6931471806f);
    p = fmaf(p, fr, 1.0f);
    return __int_as_float(__float_as_int(p) + (((int)fl) << 23));
}

__device__ __forceinline__ unsigned tf32cvt(float x) {
    unsigned r;
    asm("cvt.rna.tf32.f32 %0, %1;" : "=r"(r) : "f"(x));
    return r;
}

// D += A(16x8,row,tf32) * B(8x8,col,tf32)
__device__ __forceinline__ void mma_tf32(float* d, const unsigned* a, const unsigned* b) {
    asm volatile(
        "mma.sync.aligned.m16n8k8.row.col.f32.tf32.tf32.f32 "
        "{%0,%1,%2,%3}, {%4,%5,%6,%7}, {%8,%9}, {%0,%1,%2,%3};"
        : "+f"(d[0]), "+f"(d[1]), "+f"(d[2]), "+f"(d[3])
        : "r"(a[0]), "r"(a[1]), "r"(a[2]), "r"(a[3]), "r"(b[0]), "r"(b[1]));
}

__device__ __forceinline__ void cpa16(unsigned smem, const float* g) {
    asm volatile("cp.async.cg.shared.global [%0], [%1], 16;" :: "r"(smem), "l"(g));
}

// ---------------------------------------------------------------------------
// Elementwise tf32 rounding pass
// ---------------------------------------------------------------------------
__global__ void cvt_tf32_k(const float* __restrict__ in, float* __restrict__ out, int n4)
{
    int i = blockIdx.x * blockDim.x + threadIdx.x;
    if (i < n4) {
        float4 v = ((const float4*)in)[i];
        float4 w;
        w.x = __uint_as_float(tf32cvt(v.x));
        w.y = __uint_as_float(tf32cvt(v.y));
        w.z = __uint_as_float(tf32cvt(v.z));
        w.w = __uint_as_float(tf32cvt(v.w));
        ((float4*)out)[i] = w;
    }
}

// ---------------------------------------------------------------------------
// tf32 tensor-core GEMM, cp.async 3-stage pipeline, BK=32.
// fuse==0: plain C[M,N] store.
// fuse==1 (QKV): epilogue applies RoPE to q/k pairs (output cols 2tig,2tig+1
// are exactly the rotation pairs) and scatters tf32-rounded into the
// [B,H,T,D] q/k/v tensors. which(q/k/v) is block-uniform (1024 % 128 == 0).
// ---------------------------------------------------------------------------
#define GS 3
#define BK 32
#define ASTR 36
#define BSTR 136
#define STAGEF (128*ASTR + BK*BSTR)        // 8960 floats per stage
#define GEMM_SMEM (GS * STAGEF * 4)        // 107520 bytes

__global__ __launch_bounds__(256, 2) void tf32gemm_k(
    const float* __restrict__ A, const float* __restrict__ B,
    float* __restrict__ C,
    float* __restrict__ Qo, float* __restrict__ Ko, float* __restrict__ Vo,
    int M, int N, int K, int fuse)
{
    extern __shared__ float gsm[];
    const unsigned smbase = (unsigned)__cvta_generic_to_shared(gsm);

    const int tid = threadIdx.x;
    const int bm = blockIdx.y * 128;
    const int bn = blockIdx.x * 128;

    const int warp = tid >> 5;
    const int lane = tid & 31;
    const int grp  = lane >> 2;          // 0..7
    const int tig  = lane & 3;           // 0..3
    const int m0   = (warp >> 2) * 64;   // 0 / 64
    const int n0   = (warp & 3) * 32;    // 0..96

    const float* Abase = A + (size_t)bm * K;
    const float* Bbase = B + bn;

    float acc[4][4][4];
#pragma unroll
    for (int mt = 0; mt < 4; ++mt)
#pragma unroll
        for (int nt = 0; nt < 4; ++nt)
#pragma unroll
            for (int j = 0; j < 4; ++j) acc[mt][nt][j] = 0.f;

    const int ntiles = K >> 5;

#define ISSUE_TILE(stage, t) do {                                              \
        const float* Ag = Abase + (t) * BK;                                    \
        const float* Bg = Bbase + (size_t)((t) * BK) * N;                      \
        unsigned sb = smbase + (stage) * (STAGEF * 4);                         \
        _Pragma("unroll")                                                      \
        for (int ci = 0; ci < 4; ++ci) {                                       \
            int ai = tid + 256 * ci;                                           \
            int ar = ai >> 3, ac = (ai & 7) * 4;                               \
            cpa16(sb + (ar*ASTR + ac)*4, Ag + (size_t)ar * K + ac);            \
            int bi = tid + 256 * ci;                                           \
            int br = bi >> 5, bc = (bi & 31) * 4;                              \
            cpa16(sb + (128*ASTR + br*BSTR + bc)*4, Bg + (size_t)br * N + bc); \
        }                                                                      \
    } while (0)

#pragma unroll
    for (int s = 0; s < GS - 1; ++s) {
        ISSUE_TILE(s, s);
        asm volatile("cp.async.commit_group;" ::: "memory");
    }

    for (int t = 0; t < ntiles; ++t) {
        asm volatile("cp.async.wait_group %0;" :: "n"(GS - 2) : "memory");
        __syncthreads();

        const int tnx = t + GS - 1;
        if (tnx < ntiles) ISSUE_TILE(tnx % GS, tnx);
        asm volatile("cp.async.commit_group;" ::: "memory");

        const float* As_ = gsm + (t % GS) * STAGEF;
        const float* Bs_ = As_ + 128 * ASTR;

#pragma unroll
        for (int kk = 0; kk < 4; ++kk) {
            unsigned bf[4][2];
#pragma unroll
            for (int nt = 0; nt < 4; ++nt) {
                bf[nt][0] = __float_as_uint(Bs_[(kk*8 + tig    ) * BSTR + n0 + nt*8 + grp]);
                bf[nt][1] = __float_as_uint(Bs_[(kk*8 + tig + 4) * BSTR + n0 + nt*8 + grp]);
            }
#pragma unroll
            for (int mt = 0; mt < 4; ++mt) {
                const int r = m0 + mt*16 + grp;
                unsigned af[4];
                af[0] = __float_as_uint(As_[r       * ASTR + kk*8 + tig]);
                af[1] = __float_as_uint(As_[(r + 8) * ASTR + kk*8 + tig]);
                af[2] = __float_as_uint(As_[r       * ASTR + kk*8 + tig + 4]);
                af[3] = __float_as_uint(As_[(r + 8) * ASTR + kk*8 + tig + 4]);
#pragma unroll
                for (int nt = 0; nt < 4; ++nt)
                    mma_tf32(acc[mt][nt], af, bf[nt]);
            }
        }
    }
#undef ISSUE_TILE

    if (!fuse) {
        // Plain epilogue
#pragma unroll
        for (int mt = 0; mt < 4; ++mt) {
            const int row = bm + m0 + mt*16 + grp;
#pragma unroll
            for (int nt = 0; nt < 4; ++nt) {
                const int col = bn + n0 + nt*8 + 2*tig;
                float2 w0 = { acc[mt][nt][0], acc[mt][nt][1] };
                float2 w1 = { acc[mt][nt][2], acc[mt][nt][3] };
                *(float2*)&C[(size_t)row * N + col]       = w0;
                *(float2*)&C[(size_t)(row + 8) * N + col] = w1;
            }
        }
    } else {
        // Fused RoPE + split epilogue: cols (2tig, 2tig+1) are rope pairs.
        const int which = (bn + n0) >> 10;   // block-uniform: 0=q,1=k,2=v
        float* Out = (which == 0) ? Qo : (which == 1) ? Ko : Vo;
#pragma unroll
        for (int nt = 0; nt < 4; ++nt) {
            const int col = bn + n0 + nt*8 + 2*tig;
            const int c = col & 1023;
            const int h = c >> 6;
            const int d = c & 63;       // even
            const float inv = exp2f(-(float)d * (13.287712379549449f / 64.f));
#pragma unroll
            for (int mt = 0; mt < 4; ++mt) {
                const int row0 = bm + m0 + mt*16 + grp;
#pragma unroll
                for (int half = 0; half < 2; ++half) {
                    const int row = row0 + 8*half;
                    const float x1 = acc[mt][nt][2*half];
                    const float x2 = acc[mt][nt][2*half + 1];
                    const int bb = row >> 11;
                    const int tt = row & 2047;
                    float o0, o1;
                    if (which < 2) {
                        float sn, cs;
                        sincosf((float)tt * inv, &sn, &cs);
                        o0 = x1 * cs - x2 * sn;
                        o1 = x1 * sn + x2 * cs;
                    } else {
                        o0 = x1; o1 = x2;
                    }
                    float2 w = { __uint_as_float(tf32cvt(o0)),
                                 __uint_as_float(tf32cvt(o1)) };
                    *(float2*)(Out + ((size_t)((bb * H_ + h) * T_ + tt)) * D_ + d) = w;
                }
            }
        }
    }
}

// ---------------------------------------------------------------------------
// Tensor-core causal flash attention (tf32 mma.sync.m16n8k8).
// K/V arrive pre-rounded -> staging is pure LDG.128/STS.128.
// ---------------------------------------------------------------------------
#define SQP 76
#define SKK 76
#define SVV 72
#define ATT_SMEM ((128*SQP + 64*SKK + 64*SVV) * 4)   // 76800 bytes

__global__ __launch_bounds__(256) void attn_k(
    const float* __restrict__ Q, const float* __restrict__ K,
    const float* __restrict__ V, float* __restrict__ Y)
{
    extern __shared__ float sm[];
    float* QP = sm;                 // [128][SQP]  Q staging, then P
    float* Ks = sm + 128*SQP;       // [64][SKK]
    float* Vs = Ks + 64*SKK;        // [64][SVV]

    const int qb = (int)gridDim.x - 1 - (int)blockIdx.x;  // largest first
    const int h  = blockIdx.y;
    const int b  = blockIdx.z;
    const int bh = b * H_ + h;
    const int q0 = qb * 128;

    const float* Qg = Q + (size_t)bh * T_ * D_;
    const float* Kg = K + (size_t)bh * T_ * D_;
    const float* Vg = V + (size_t)bh * T_ * D_;

    const int tid  = threadIdx.x;
    const int warp = tid >> 5;
    const int lane = tid & 31;
    const int grp  = lane >> 2;      // 0..7
    const int tig  = lane & 3;       // 0..3

    // Stage Q tile (128x64) into QP
#pragma unroll
    for (int i = 0; i < 8; ++i) {
        int idx = tid + 256 * i;
        int row = idx >> 4;
        int c4  = (idx & 15) * 4;
        *(float4*)&QP[row * SQP + c4] = *(const float4*)&Qg[(size_t)(q0 + row) * D_ + c4];
    }
    __syncthreads();

    // Hoist Q A-fragments (scale folded: 1/8 * log2(e)), re-round to tf32
    const float scale2 = 0.125f * 1.4426950408889634f;
    unsigned qa[8][4];
    {
        const int r0 = 16 * warp + grp;
#pragma unroll
        for (int ks = 0; ks < 8; ++ks) {
            int cbase = ks * 8 + tig;
            qa[ks][0] = tf32cvt(QP[r0 * SQP + cbase] * scale2);
            qa[ks][1] = tf32cvt(QP[(r0 + 8) * SQP + cbase] * scale2);
            qa[ks][2] = tf32cvt(QP[r0 * SQP + cbase + 4] * scale2);
            qa[ks][3] = tf32cvt(QP[(r0 + 8) * SQP + cbase + 4] * scale2);
        }
    }

    float m0 = -INFINITY, m1 = -INFINITY, l0 = 0.f, l1 = 0.f;
    float oa[8][4];
#pragma unroll
    for (int nt = 0; nt < 8; ++nt)
#pragma unroll
        for (int j = 0; j < 4; ++j) oa[nt][j] = 0.f;

    const int nk = 2 * qb + 2;              // 64-wide k tiles
    const int rwarp0 = q0 + 16 * warp;      // warp's first global row

    for (int kt = 0; kt < nk; ++kt) {
        const int k0 = kt * 64;
        __syncthreads();

        // Load K,V tiles (already tf32 bits): raw float4 copies
#pragma unroll
        for (int i = 0; i < 4; ++i) {
            int idx = tid + 256 * i;
            int row = idx >> 4;
            int c4  = (idx & 15) * 4;
            *(float4*)&Ks[row * SKK + c4] = *(const float4*)&Kg[(size_t)(k0 + row) * D_ + c4];
            *(float4*)&Vs[row * SVV + c4] = *(const float4*)&Vg[(size_t)(k0 + row) * D_ + c4];
        }
        __syncthreads();

        // S = (Q*scale) @ K^T
        float s[8][4];
#pragma unroll
        for (int nt = 0; nt < 8; ++nt)
#pragma unroll
            for (int j = 0; j < 4; ++j) s[nt][j] = 0.f;

#pragma unroll
        for (int ks = 0; ks < 8; ++ks) {
#pragma unroll
            for (int nt = 0; nt < 8; ++nt) {
                int naddr = (nt * 8 + grp) * SKK + ks * 8 + tig;
                unsigned bfr[2];
                bfr[0] = __float_as_uint(Ks[naddr]);
                bfr[1] = __float_as_uint(Ks[naddr + 4]);
                mma_tf32(s[nt], qa[ks], bfr);
            }
        }

        // Causal mask (gate on warp's MIN row)
        if (k0 + 63 > rwarp0) {
            const int r0g = rwarp0 + grp;
#pragma unroll
            for (int nt = 0; nt < 8; ++nt) {
                int cb = k0 + nt * 8 + 2 * tig;
                if (cb     > r0g)     s[nt][0] = -INFINITY;
                if (cb + 1 > r0g)     s[nt][1] = -INFINITY;
                if (cb     > r0g + 8) s[nt][2] = -INFINITY;
                if (cb + 1 > r0g + 8) s[nt][3] = -INFINITY;
            }
        }

        // Warp-private online softmax
        float rm0 = -INFINITY, rm1 = -INFINITY;
#pragma unroll
        for (int nt = 0; nt < 8; ++nt) {
            rm0 = fmaxf(rm0, fmaxf(s[nt][0], s[nt][1]));
            rm1 = fmaxf(rm1, fmaxf(s[nt][2], s[nt][3]));
        }
        rm0 = fmaxf(rm0, __shfl_xor_sync(0xffffffffu, rm0, 1));
        rm0 = fmaxf(rm0, __shfl_xor_sync(0xffffffffu, rm0, 2));
        rm1 = fmaxf(rm1, __shfl_xor_sync(0xffffffffu, rm1, 1));
        rm1 = fmaxf(rm1, __shfl_xor_sync(0xffffffffu, rm1, 2));

        float mn0 = fmaxf(m0, rm0), mn1 = fmaxf(m1, rm1);
        float al0 = fexp2(m0 - mn0), al1 = fexp2(m1 - mn1);
        m0 = mn0; m1 = mn1;

        float rs0 = 0.f, rs1 = 0.f;
#pragma unroll
        for (int nt = 0; nt < 8; ++nt) {
            s[nt][0] = fexp2(s[nt][0] - mn0);
            s[nt][1] = fexp2(s[nt][1] - mn0);
            s[nt][2] = fexp2(s[nt][2] - mn1);
            s[nt][3] = fexp2(s[nt][3] - mn1);
            rs0 += s[nt][0] + s[nt][1];
            rs1 += s[nt][2] + s[nt][3];
        }
        rs0 += __shfl_xor_sync(0xffffffffu, rs0, 1);
        rs0 += __shfl_xor_sync(0xffffffffu, rs0, 2);
        rs1 += __shfl_xor_sync(0xffffffffu, rs1, 1);
        rs1 += __shfl_xor_sync(0xffffffffu, rs1, 2);

        l0 = l0 * al0 + rs0;
        l1 = l1 * al1 + rs1;
#pragma unroll
        for (int nt = 0; nt < 8; ++nt) {
            oa[nt][0] *= al0; oa[nt][1] *= al0;
            oa[nt][2] *= al1; oa[nt][3] *= al1;
        }

        // Write P (tf32 bits) into QP — warp-private rows
        {
            const int pr0 = 16 * warp + grp;
#pragma unroll
            for (int nt = 0; nt < 8; ++nt) {
                int cb = nt * 8 + 2 * tig;
                float2 w0 = { __uint_as_float(tf32cvt(s[nt][0])),
                              __uint_as_float(tf32cvt(s[nt][1])) };
                float2 w1 = { __uint_as_float(tf32cvt(s[nt][2])),
                              __uint_as_float(tf32cvt(s[nt][3])) };
                *(float2*)&QP[pr0 * SQP + cb]       = w0;
                *(float2*)&QP[(pr0 + 8) * SQP + cb] = w1;
            }
        }
        __syncwarp();

        // O += P @ V
#pragma unroll
        for (int ks = 0; ks < 8; ++ks) {
            const int pb = (16 * warp + grp) * SQP + ks * 8 + tig;
            unsigned pa[4];
            pa[0] = __float_as_uint(QP[pb]);
            pa[1] = __float_as_uint(QP[pb + 8 * SQP]);
            pa[2] = __float_as_uint(QP[pb + 4]);
            pa[3] = __float_as_uint(QP[pb + 8 * SQP + 4]);
#pragma unroll
            for (int nt = 0; nt < 8; ++nt) {
                int vaddr = (ks * 8 + tig) * SVV + nt * 8 + grp;
                unsigned bfr[2];
                bfr[0] = __float_as_uint(Vs[vaddr]);
                bfr[1] = __float_as_uint(Vs[vaddr + 4 * SVV]);
                mma_tf32(oa[nt], pa, bfr);
            }
        }
    }

    // Epilogue: normalize, tf32-round (proj GEMM input), write [B,T,H,D]
    const float i0 = 1.f / l0, i1 = 1.f / l1;
    const int t0 = rwarp0 + grp;
#pragma unroll
    for (int nt = 0; nt < 8; ++nt) {
        int d = nt * 8 + 2 * tig;
        float2 w0 = { __uint_as_float(tf32cvt(oa[nt][0] * i0)),
                      __uint_as_float(tf32cvt(oa[nt][1] * i0)) };
        float2 w1 = { __uint_as_float(tf32cvt(oa[nt][2] * i1)),
                      __uint_as_float(tf32cvt(oa[nt][3] * i1)) };
        *(float2*)(Y + ((size_t)(b * T_ + t0)     * H_ + h) * D_ + d) = w0;
        *(float2*)(Y + ((size_t)(b * T_ + t0 + 8) * H_ + h) * D_ + d) = w1;
    }
}

// ---------------------------------------------------------------------------
extern "C" void kernel_launch(void* const* d_in, const int* in_sizes, int n_in,
                              void* d_out, int out_size)
{
    const float* x      = (const float*)d_in[0];   // [B,T,C]
    const float* W_attn = (const float*)d_in[1];   // [C,3C]
    const float* W_proj = (const float*)d_in[2];   // [C,C]
    float* out = (float*)d_out;                    // [B,T,C]

    float *q, *k, *v, *y, *xc, *wac, *wpc;
    cudaGetSymbolAddress((void**)&q,   g_q);
    cudaGetSymbolAddress((void**)&k,   g_k);
    cudaGetSymbolAddress((void**)&v,   g_v);
    cudaGetSymbolAddress((void**)&y,   g_y);
    cudaGetSymbolAddress((void**)&xc,  g_xc);
    cudaGetSymbolAddress((void**)&wac, g_wac);
    cudaGetSymbolAddress((void**)&wpc, g_wpc);

    cudaFuncSetAttribute(attn_k, cudaFuncAttributeMaxDynamicSharedMemorySize, ATT_SMEM);
    cudaFuncSetAttribute(tf32gemm_k, cudaFuncAttributeMaxDynamicSharedMemorySize, GEMM_SMEM);

    // 0) Pre-round GEMM inputs to tf32
    cvt_tf32_k<<<(BT_*C_/4 + 255)/256, 256>>>(x, xc, BT_*C_/4);
    cvt_tf32_k<<<(C_*F3_/4 + 255)/256, 256>>>(W_attn, wac, C_*F3_/4);
    cvt_tf32_k<<<(C_*C_/4 + 255)/256, 256>>>(W_proj, wpc, C_*C_/4);

    // 1) QKV GEMM with fused RoPE+split epilogue -> q,k,v in [B,H,T,D]
    {
        dim3 grid(F3_ / 128, BT_ / 128);
        tf32gemm_k<<<grid, 256, GEMM_SMEM>>>(xc, wac, nullptr, q, k, v,
                                             BT_, F3_, C_, 1);
    }
    // 2) Tensor-core causal flash attention (q-tile 128)
    {
        dim3 grid(T_ / 128, H_, B_);
        attn_k<<<grid, 256, ATT_SMEM>>>(q, k, v, y);
    }
    // 3) Projection GEMM (plain epilogue): [8192,1024] @ [1024,1024]
    {
        dim3 grid(C_ / 128, BT_ / 128);
        tf32gemm_k<<<grid, 256, GEMM_SMEM>>>(y, wpc, out, nullptr, nullptr, nullptr,
                                             BT_, C_, C_, 0);
    }
}